// round 12
// baseline (speedup 1.0000x reference)
#include <cuda_runtime.h>
#include <cuda_fp16.h>
#include <math.h>

#define LSEQ 45000

// ---------------- device scratch (no allocs allowed) ----------------
__device__ uint4 d_posh4[1048576];          // [2][512][512] * 32B (16 halfs: 15 feats + sign)
__device__ int   d_topk[2][2][256];
__device__ int   d_idxg[2][512];
__device__ float d_emb[2*512*32];
__device__ __align__(16) __half d_kkh[2][2*4*32*512];   // [parity][b*4+h][d][j] fp16
__device__ __align__(16) __half d_vvh[2][2*4*32*512];
__device__ float d_qcb[2][2*4*512*32];      // [parity] q*scale + rcb  [bh][i][d]
__device__ float d_qrl[2][2*512*4*32];      // [parity][b][i][h][30 used]
__device__ float d_cc[24];                  // 0..4 c1, 5..9 lz, 10..14 rate, 15..19 conc-1
__device__ int   d_pmaxbits;                // global gamma max (positive-float bits)

__device__ __forceinline__ __half2 u2h(unsigned u) { return *reinterpret_cast<__half2*>(&u); }
__device__ __forceinline__ unsigned h2u(__half2 h) { return *reinterpret_cast<unsigned*>(&h); }

// ---------------- prologue: blocks 0-3 top-256 select, blocks 4-35 basis setup ----------------
#define TK_CAP 2816
__global__ void __launch_bounds__(1024) prologue_kernel(const float* __restrict__ att) {
    extern __shared__ unsigned char tks[];
    int t = threadIdx.x, lane = t & 31;

    if (blockIdx.x >= 4) {
        float* red = (float*)tks;
        int bid = blockIdx.x - 4;
        double L2S = log(45000.0) / log(2.0);
        float c1[5], lz[5], rate[5], cm1[5];
        for (int k = 0; k < 5; k++) {
            double lin = 3.0 + (L2S - 3.0) * ((double)k / 4.0);
            float hl = (float)exp2(lin);
            c1[k] = -0.69314718055994531f / hl;
            double mean = 9000.0 * (k + 1);
            double sd = 4500.0;
            float conc = (float)((mean / sd) * (mean / sd));
            float rt = (float)(mean / (sd * sd));
            rate[k] = rt; cm1[k] = conc - 1.0f;
            lz[k] = lgammaf(conc) - conc * logf(rt);
        }
        float m = 1e-8f;
        for (int a_ = bid * 1024 + t; a_ < LSEQ; a_ += 32768) {
            if (a_ == 0) continue;
            float a = (float)a_;
            float la = logf(a);
            for (int k = 0; k < 5; k++) {
                float p = expf(cm1[k] * la - rate[k] * a - lz[k]) + 1e-8f;
                m = fmaxf(m, p);
            }
        }
        red[t] = m; __syncthreads();
        for (int s = 512; s > 0; s >>= 1) {
            if (t < s) red[t] = fmaxf(red[t], red[t + s]);
            __syncthreads();
        }
        if (t == 0) atomicMax(&d_pmaxbits, __float_as_int(red[0]));
        if (bid == 0 && t == 0) {
            for (int k = 0; k < 5; k++) { d_cc[k] = c1[k]; d_cc[5+k] = lz[k]; d_cc[10+k] = rate[k]; d_cc[15+k] = cm1[k]; }
        }
        return;
    }

    unsigned* hist = (unsigned*)tks;                                     // 8192 u
    unsigned long long* cand = (unsigned long long*)(tks + 32768);       // 2816
    unsigned* ps = (unsigned*)(tks + 32768 + 22528);                     // 256
    __shared__ unsigned thrT;
    __shared__ int cnt, ocnt, rem_s;
    __shared__ unsigned long long pref_s;
    int b = blockIdx.x >> 1, ch = (blockIdx.x & 1) + 1;
    const float* vals = att + (size_t)(b * 3 + ch) * LSEQ;
    for (int i = t; i < 8192; i += 1024) hist[i] = 0;
    if (t == 0) { cnt = 0; ocnt = 0; pref_s = 0ull; rem_s = 256; }
    __syncthreads();
    for (int j = t; j < LSEQ; j += 1024) {
        unsigned u = __float_as_uint(vals[j]);
        u = (u & 0x80000000u) ? ~u : (u | 0x80000000u);
        atomicAdd(&hist[u >> 19], 1u);
    }
    __syncthreads();
    if (t < 256) {
        unsigned sum = 0;
        int base = 8191 - t * 32;
        for (int k = 0; k < 32; k++) sum += hist[base - k];
        ps[t] = sum;
    }
    __syncthreads();
    if (t < 32) {
        unsigned s = 0;
        #pragma unroll
        for (int k = 0; k < 8; k++) s += ps[lane * 8 + k];
        unsigned pre = s;
        #pragma unroll
        for (int o = 1; o < 32; o <<= 1) { unsigned v = __shfl_up_sync(0xffffffffu, pre, o); if (lane >= o) pre += v; }
        bool hit = (pre >= 256u) && (pre - s) < 256u;
        unsigned mk = __ballot_sync(0xffffffffu, hit);
        if (lane == (__ffs(mk) - 1)) {
            unsigned cum = pre - s;
            int T = 0;
            for (int k = 0; k < 8; k++) {
                int ci = lane * 8 + k;
                if (cum + ps[ci] >= 256u) {
                    int base = 8191 - ci * 32;
                    for (int kk = 0; kk < 32; kk++) { cum += hist[base - kk]; if (cum >= 256u) { T = base - kk; break; } }
                    break;
                }
                cum += ps[ci];
            }
            thrT = (unsigned)T;
        }
    }
    __syncthreads();
    unsigned T = thrT;
    for (int j = t; j < LSEQ; j += 1024) {
        unsigned u = __float_as_uint(vals[j]);
        u = (u & 0x80000000u) ? ~u : (u | 0x80000000u);
        if ((u >> 19) >= T) {
            int pi = atomicAdd(&cnt, 1);
            if (pi < TK_CAP) cand[pi] = (((unsigned long long)u) << 32) | (unsigned)(0xFFFFFFFFu - (unsigned)j);
        }
    }
    __syncthreads();
    int n = cnt < TK_CAP ? cnt : TK_CAP;
    for (int shift = 56; shift >= 0; shift -= 8) {
        if (t < 256) hist[t] = 0;
        __syncthreads();
        unsigned long long p = pref_s;
        unsigned long long mh = (shift == 56) ? 0ull : ~((1ull << (shift + 8)) - 1ull);
        for (int i = t; i < n; i += 1024) {
            unsigned long long k = cand[i];
            if ((k & mh) == p) atomicAdd(&hist[(unsigned)(k >> shift) & 255u], 1u);
        }
        __syncthreads();
        if (t < 32) {
            int r = rem_s;
            unsigned s = 0;
            #pragma unroll
            for (int k = 0; k < 8; k++) s += hist[255 - (lane * 8 + k)];
            unsigned pre = s;
            #pragma unroll
            for (int o = 1; o < 32; o <<= 1) { unsigned v = __shfl_up_sync(0xffffffffu, pre, o); if (lane >= o) pre += v; }
            bool hit = ((int)pre >= r) && (int)(pre - s) < r;
            unsigned mk = __ballot_sync(0xffffffffu, hit);
            if (lane == (__ffs(mk) - 1)) {
                unsigned cum = pre - s;
                for (int k = 0; k < 8; k++) {
                    int bin = 255 - (lane * 8 + k);
                    cum += hist[bin];
                    if ((int)cum >= r) { rem_s = r - (int)(cum - hist[bin]); pref_s = p | ((unsigned long long)bin << shift); break; }
                }
            }
        }
        __syncthreads();
    }
    unsigned long long kth = pref_s;
    for (int i = t; i < n; i += 1024) {
        if (cand[i] >= kth) {
            int pi = atomicAdd(&ocnt, 1);
            if (pi < 256) d_topk[b][ch - 1][pi] = (int)(0xFFFFFFFFu - (unsigned)(cand[i] & 0xFFFFFFFFull));
        }
    }
}

// ---------------- merge+sort 512 indices, gather embeddings ----------------
__global__ void __launch_bounds__(256) sortgather_kernel(const float* __restrict__ x_skip) {
    int b = blockIdx.x, t = threadIdx.x;
    __shared__ int s[512];
    s[t] = d_topk[b][0][t];
    s[256 + t] = d_topk[b][1][t];
    __syncthreads();
    for (int k = 2; k <= 512; k <<= 1) {
        for (int j = k >> 1; j > 0; j >>= 1) {
            #pragma unroll
            for (int half = 0; half < 2; half++) {
                int idx = half * 256 + t;
                int ixj = idx ^ j;
                if (ixj > idx) {
                    int a = s[idx], c = s[ixj];
                    bool up = ((idx & k) == 0);
                    if ((a > c) == up) { s[idx] = c; s[ixj] = a; }
                }
            }
            __syncthreads();
        }
    }
    d_idxg[b][t] = s[t];
    d_idxg[b][256 + t] = s[256 + t];
    __syncthreads();
    for (int q = t; q < 512 * 32; q += 256) {
        int i = q >> 5, c = q & 31;
        d_emb[(b * 512 + i) * 32 + c] = x_skip[((size_t)b * 32 + c) * LSEQ + s[i]];
    }
}

// ---------------- positional basis features (layer-invariant, fp16 packed) ----------------
__global__ void __launch_bounds__(256) pos_kernel() {
    unsigned int id = blockIdx.x * 256u + threadIdx.x;   // 2*512*512 threads
    int b = id >> 18;
    unsigned int r = id & 262143u;
    int i = r >> 9, j = r & 511;
    int d = d_idxg[b][i] - d_idxg[b][j];
    float a = fabsf((float)d);
    float sg = (d > 0) ? 1.f : ((d < 0) ? -1.f : 0.f);
    float f[16];
    #pragma unroll
    for (int k = 0; k < 5; k++) f[k] = expf(d_cc[k] * a);
    f[5] = (1.f  > a) ? 1.f : 0.f;
    f[6] = (3.f  > a) ? 1.f : 0.f;
    f[7] = (7.f  > a) ? 1.f : 0.f;
    f[8] = (15.f > a) ? 1.f : 0.f;
    f[9] = (31.f > a) ? 1.f : 0.f;
    float la = logf(a);                 // a==0 -> -inf -> exp -> 0 (matches xlogy path)
    float invp = 1.0f / __int_as_float(d_pmaxbits);
    #pragma unroll
    for (int k = 0; k < 5; k++) {
        float lp = d_cc[15 + k] * la - d_cc[10 + k] * a;
        f[10 + k] = (expf(lp - d_cc[5 + k]) + 1e-8f) * invp;
    }
    f[15] = sg;
    unsigned u[8];
    #pragma unroll
    for (int k = 0; k < 8; k++) u[k] = h2u(__floats2half2_rn(f[2 * k], f[2 * k + 1]));
    uint4* o = d_posh4 + (size_t)id * 2u;
    o[0] = make_uint4(u[0], u[1], u[2], u[3]);
    o[1] = make_uint4(u[4], u[5], u[6], u[7]);
}

// ---------------- per-layer mega-kernel: attn(lm) + mlp(lm) + qkv(lq) ----------------
// block = 8 tokens x ALL 4 heads, 512 threads, attention in 2 head-pair phases.
__global__ void __launch_bounds__(512, 1) layer_kernel(
    const float* __restrict__ Wo, const float* __restrict__ bo,
    const float* __restrict__ ln2g, const float* __restrict__ ln2b,
    const float* __restrict__ W1, const float* __restrict__ b1,
    const float* __restrict__ W2, const float* __restrict__ b2,
    const float* __restrict__ ln1g, const float* __restrict__ ln1b,
    const float* __restrict__ Wq, const float* __restrict__ Wk, const float* __restrict__ Wv,
    const float* __restrict__ Wrel, const float* __restrict__ rcb, const float* __restrict__ rpb,
    float* __restrict__ out,
    int lm, int lq, int do_am, int do_qkv)
{
    extern __shared__ __align__(16) unsigned char smraw[];
    __half* Kh = (__half*)smraw;                        // 65536 B (2 heads x 32d x 512j)
    __half* Vh = (__half*)(smraw + 65536);              // 65536 B
    float* smf = (float*)smraw;
    float* ats = smf + 32768;                           // 1024
    float* es  = smf + 33792;                           // 256
    float* h2s = smf + 34048;                           // 256
    float* tbs = smf + 34304;                           // 4096
    float* red = smf + 38400;                           // 4096
    float* qp  = smf + 42496;                           // 1024
    float* Wrs = smf + 43520;                           // 3870
    float* qcs = smf + 47392;                           // 1024 (32 units x 32)
    unsigned* qAh = (unsigned*)(smf + 48416);           // 256
    unsigned* qBh = (unsigned*)(smf + 48672);           // 256  -> 48928 f = 195712 B
    int t = threadIdx.x, lane = t & 31, w = t >> 5;
    int i0 = blockIdx.x * 8, b = blockIdx.y;
    int par_a = lm & 1, par_q = lq & 1;

    // hoist Wrel staging (independent of everything)
    if (do_qkv) {
        for (int q = t; q < 3840; q += 512) {
            int f = q >> 7, c = q & 127;
            Wrs[f * 129 + c] = Wrel[lq * 3840 + q];
        }
    }

    if (do_am) {
        // ---- attention: stage per-row q-vectors ----
        for (int q = t; q < 1024; q += 512) {
            int unit = q >> 5, d = q & 31;
            int head = unit >> 3, row = unit & 7;
            qcs[q] = d_qcb[par_a][((b * 4 + head) * 512 + i0 + row) * 32 + d];
        }
        if (t < 256) {
            int unit = t >> 3, p8 = t & 7;
            int head = unit >> 3, row = unit & 7;
            const float* qr = d_qrl[par_a] + ((b * 512 + i0 + row) * 4 + head) * 32;
            int f0 = 2 * p8, f1 = f0 + 1;
            float a0 = qr[f0],      a1 = (f1 < 15) ? qr[f1] : 0.f;
            float b0 = qr[15 + f0], b1 = (f1 < 15) ? qr[15 + f1] : 0.f;
            qAh[unit * 8 + p8] = h2u(__floats2half2_rn(a0, a1));
            qBh[unit * 8 + p8] = h2u(__floats2half2_rn(b0, b1));
        }
        int row = w & 7, hl = w >> 3;
        for (int p = 0; p < 2; p++) {
            if (p) __syncthreads();   // phase-0 PV reads done before overwrite
            {
                const uint4* kg = (const uint4*)(d_kkh[par_a] + (size_t)(b * 4 + 2 * p) * 16384);
                const uint4* vg = (const uint4*)(d_vvh[par_a] + (size_t)(b * 4 + 2 * p) * 16384);
                uint4* ks4 = (uint4*)Kh; uint4* vs4 = (uint4*)Vh;
                for (int q = t; q < 4096; q += 512) { ks4[q] = kg[q]; vs4[q] = vg[q]; }
            }
            __syncthreads();
            int head = 2 * p + hl;
            int unit = head * 8 + row;
            const __half* Krow = Kh + hl * 16384;
            const __half* Vrow = Vh + hl * 16384;
            float s[16];
            #pragma unroll
            for (int q = 0; q < 16; q++) s[q] = 0.f;
            // content QK
            for (int d = 0; d < 32; d++) {
                float qv = qcs[unit * 32 + d];
                const uint2* kr = (const uint2*)(Krow + d * 512);
                #pragma unroll
                for (int ch = 0; ch < 4; ch++) {
                    uint2 kk = kr[ch * 32 + lane];
                    float2 fa = __half22float2(u2h(kk.x));
                    float2 fb = __half22float2(u2h(kk.y));
                    s[ch*4+0] += qv * fa.x; s[ch*4+1] += qv * fa.y;
                    s[ch*4+2] += qv * fb.x; s[ch*4+3] += qv * fb.y;
                }
            }
            // rel
            {
                __half2 qa[8], qb[8];
                #pragma unroll
                for (int k = 0; k < 8; k++) { qa[k] = u2h(qAh[unit * 8 + k]); qb[k] = u2h(qBh[unit * 8 + k]); }
                const uint4* prow = d_posh4 + 2 * (size_t)((b * 512 + i0 + row) * 512);
                #pragma unroll
                for (int ch = 0; ch < 4; ch++) {
                    #pragma unroll
                    for (int u = 0; u < 4; u++) {
                        int j = ch * 128 + lane * 4 + u;
                        uint4 A = prow[2 * j], B = prow[2 * j + 1];
                        __half2 sA = __hmul2(u2h(A.x), qa[0]);
                        sA = __hfma2(u2h(A.y), qa[1], sA); sA = __hfma2(u2h(A.z), qa[2], sA);
                        sA = __hfma2(u2h(A.w), qa[3], sA); sA = __hfma2(u2h(B.x), qa[4], sA);
                        sA = __hfma2(u2h(B.y), qa[5], sA); sA = __hfma2(u2h(B.z), qa[6], sA);
                        sA = __hfma2(u2h(B.w), qa[7], sA);
                        __half2 sB = __hmul2(u2h(A.x), qb[0]);
                        sB = __hfma2(u2h(A.y), qb[1], sB); sB = __hfma2(u2h(A.z), qb[2], sB);
                        sB = __hfma2(u2h(A.w), qb[3], sB); sB = __hfma2(u2h(B.x), qb[4], sB);
                        sB = __hfma2(u2h(B.y), qb[5], sB); sB = __hfma2(u2h(B.z), qb[6], sB);
                        sB = __hfma2(u2h(B.w), qb[7], sB);
                        float2 fA = __half22float2(sA), fB = __half22float2(sB);
                        float sg = __high2float(u2h(B.w));
                        s[ch * 4 + u] += (fA.x + fA.y) + sg * (fB.x + fB.y);
                    }
                }
            }
            // softmax
            float m = -3.0e38f;
            #pragma unroll
            for (int q = 0; q < 16; q++) m = fmaxf(m, s[q]);
            #pragma unroll
            for (int o = 16; o > 0; o >>= 1) m = fmaxf(m, __shfl_xor_sync(0xffffffffu, m, o));
            float su = 0.f;
            #pragma unroll
            for (int q = 0; q < 16; q++) { s[q] = expf(s[q] - m); su += s[q]; }
            #pragma unroll
            for (int o = 16; o > 0; o >>= 1) su += __shfl_xor_sync(0xffffffffu, su, o);
            float inv = 1.f / su;
            // PV: acc[d] = lane-partial over its j's
            float v[32];
            for (int d = 0; d < 32; d++) {
                const uint2* vr = (const uint2*)(Vrow + d * 512);
                float a0 = 0.f;
                #pragma unroll
                for (int ch = 0; ch < 4; ch++) {
                    uint2 vv = vr[ch * 32 + lane];
                    float2 fa = __half22float2(u2h(vv.x));
                    float2 fb = __half22float2(u2h(vv.y));
                    a0 += s[ch*4+0]*fa.x + s[ch*4+1]*fa.y + s[ch*4+2]*fb.x + s[ch*4+3]*fb.y;
                }
                v[d] = a0;
            }
            // butterfly transpose-reduce: lane L ends with sum for d=L
            #pragma unroll
            for (int mm = 16; mm >= 1; mm >>= 1) {
                #pragma unroll
                for (int k = 0; k < mm; k++) {
                    float give = (lane & mm) ? v[k] : v[k + mm];
                    float got = __shfl_xor_sync(0xffffffffu, give, mm);
                    v[k] = (lane & mm) ? (v[k + mm] + got) : (v[k] + got);
                }
            }
            ats[row * 128 + head * 32 + lane] = v[0] * inv;
        }
        __syncthreads();   // ats complete before Wo
    }

    // ---- MLP ----
    int oi = t >> 1, hf = t & 1;
    int wo_tok = oi >> 5, wo_c = oi & 31;
    if (do_am) {
        // independent prefetches
        float wcol[32];
        {
            const float* w1 = W1 + lm * 16384;
            #pragma unroll
            for (int cc = 0; cc < 32; cc++) wcol[cc] = w1[cc * 512 + t];
        }
        float resid = (hf == 0) ? d_emb[(b * 512 + i0 + wo_tok) * 32 + wo_c] : 0.f;
        // Wo + residual: 2-way m-split, lane-pair combine
        {
            const float* wo = Wo + lm * 4096;
            int mb = hf * 64;
            float acc = 0.f;
            #pragma unroll 16
            for (int m = 0; m < 64; m++) acc += ats[wo_tok * 128 + mb + m] * wo[(mb + m) * 32 + wo_c];
            acc += __shfl_xor_sync(0xffffffffu, acc, 1);
            if (hf == 0) es[oi] = resid + acc + bo[lm * 32 + wo_c];
        }
        __syncthreads();
        // LN2
        if (w < 8) {
            float x = es[w * 32 + lane];
            float s1 = x;
            #pragma unroll
            for (int o = 16; o > 0; o >>= 1) s1 += __shfl_xor_sync(0xffffffffu, s1, o);
            float mu = s1 * (1.f / 32.f);
            float dd = x - mu;
            float s2 = dd * dd;
            #pragma unroll
            for (int o = 16; o > 0; o >>= 1) s2 += __shfl_xor_sync(0xffffffffu, s2, o);
            float rs = rsqrtf(s2 * (1.f / 32.f) + 1e-5f);
            h2s[w * 32 + lane] = dd * rs * ln2g[lm * 32 + lane] + ln2b[lm * 32 + lane];
        }
        __syncthreads();
        // W1 + gelu (weights in regs)
        {
            float bb = b1[lm * 512 + t];
            #pragma unroll
            for (int tok = 0; tok < 8; tok++) {
                float s = bb;
                #pragma unroll
                for (int cc = 0; cc < 32; cc++) s += h2s[tok * 32 + cc] * wcol[cc];
                tbs[tok * 512 + t] = 0.5f * s * (1.f + erff(s * 0.70710678118654752f));
            }
        }
        __syncthreads();
        // W2: 16 warps x 32 rows m-split
        {
            const float* w2 = W2 + lm * 16384;
            int m0 = w * 32;
            float accw[8];
            #pragma unroll
            for (int tok = 0; tok < 8; tok++) accw[tok] = 0.f;
            #pragma unroll 4
            for (int mm = 0; mm < 32; mm++) {
                float w2v = w2[(m0 + mm) * 32 + lane];
                #pragma unroll
                for (int tok = 0; tok < 8; tok++) accw[tok] += tbs[tok * 512 + m0 + mm] * w2v;
            }
            #pragma unroll
            for (int tok = 0; tok < 8; tok++) red[(w * 8 + tok) * 32 + lane] = accw[tok];
        }
        __syncthreads();
        if (t < 256) {
            int tok = t >> 5, c = t & 31;
            float s = 0.f;
            #pragma unroll
            for (int ww = 0; ww < 16; ww++) s += red[(ww * 8 + tok) * 32 + c];
            float ne = es[t] + s + b2[lm * 32 + c];
            if (do_qkv) {
                d_emb[(b * 512 + i0 + tok) * 32 + c] = ne;
                es[t] = ne;
            } else {
                out[((size_t)b * 32 + c) * LSEQ + d_idxg[b][i0 + tok]] = ne;
            }
        }
    } else {
        if (t < 256) es[t] = d_emb[(b * 512 + i0) * 32 + t];
    }
    __syncthreads();

    if (!do_qkv) return;

    // ---- LN1 + QKV(lq) ----
    if (w < 8) {
        float x = es[w * 32 + lane];
        float s1 = x;
        #pragma unroll
        for (int o = 16; o > 0; o >>= 1) s1 += __shfl_xor_sync(0xffffffffu, s1, o);
        float mu = s1 * (1.f / 32.f);
        float dd = x - mu;
        float s2 = dd * dd;
        #pragma unroll
        for (int o = 16; o > 0; o >>= 1) s2 += __shfl_xor_sync(0xffffffffu, s2, o);
        float rs = rsqrtf(s2 * (1.f / 32.f) + 1e-5f);
        h2s[w * 32 + lane] = dd * rs * ln1g[lq * 32 + lane] + ln1b[lq * 32 + lane];
    }
    __syncthreads();
    {
        int c = t & 127, tg = t >> 7;
        int hh = c >> 5, dd = c & 31;
        int bh = b * 4 + hh;
        float rc = rcb[(lq * 4 + hh) * 32 + dd];
        float rp = rpb[(lq * 4 + hh) * 32 + dd];
        const float* wq = Wq + lq * 4096;
        const float* wk = Wk + lq * 4096;
        const float* wv = Wv + lq * 4096;
        float accq[2] = {0.f, 0.f}, acck[2] = {0.f, 0.f}, accv[2] = {0.f, 0.f};
        #pragma unroll 8
        for (int cc = 0; cc < 32; cc++) {
            float a = wq[cc * 128 + c], kwe = wk[cc * 128 + c], vwe = wv[cc * 128 + c];
            #pragma unroll
            for (int tk = 0; tk < 2; tk++) {
                float hc = h2s[(tg * 2 + tk) * 32 + cc];
                accq[tk] += hc * a; acck[tk] += hc * kwe; accv[tk] += hc * vwe;
            }
        }
        #pragma unroll
        for (int tk = 0; tk < 2; tk++) {
            int tok = tg * 2 + tk;
            float q = accq[tk] * 0.17677669529663687f;
            d_qcb[par_q][(bh * 512 + i0 + tok) * 32 + dd] = q + rc;
            qp[tok * 128 + c] = q + rp;
        }
        *(unsigned*)&d_kkh[par_q][(bh * 32 + dd) * 512 + i0 + tg * 2] = h2u(__floats2half2_rn(acck[0], acck[1]));
        *(unsigned*)&d_vvh[par_q][(bh * 32 + dd) * 512 + i0 + tg * 2] = h2u(__floats2half2_rn(accv[0], accv[1]));
    }
    __syncthreads();
    if (lane < 30) {
        int f = lane, tok = w >> 1, h2b = (w & 1) * 2;
        #pragma unroll
        for (int k = 0; k < 2; k++) {
            int hh2 = h2b + k;
            float s = 0.f;
            #pragma unroll
            for (int d2 = 0; d2 < 32; d2++)
                s += Wrs[f * 129 + hh2 * 32 + d2] * qp[tok * 128 + hh2 * 32 + d2];
            d_qrl[par_q][((b * 512 + i0 + tok) * 4 + hh2) * 32 + f] = s;
        }
    }
}

// ---------------- launch ----------------
extern "C" void kernel_launch(void* const* d_in, const int* in_sizes, int n_in,
                              void* d_out, int out_size) {
    (void)in_sizes; (void)n_in;
    const float* x_skip    = (const float*)d_in[0];
    const float* attention = (const float*)d_in[1];
    const float* ln1g = (const float*)d_in[2];
    const float* ln1b = (const float*)d_in[3];
    const float* Wq   = (const float*)d_in[4];
    const float* Wk   = (const float*)d_in[5];
    const float* Wv   = (const float*)d_in[6];
    const float* Wrel = (const float*)d_in[7];
    const float* rcb  = (const float*)d_in[8];
    const float* rpb  = (const float*)d_in[9];
    const float* Wo   = (const float*)d_in[10];
    const float* bo   = (const float*)d_in[11];
    const float* ln2g = (const float*)d_in[12];
    const float* ln2b = (const float*)d_in[13];
    const float* W1   = (const float*)d_in[14];
    const float* b1   = (const float*)d_in[15];
    const float* W2   = (const float*)d_in[16];
    const float* b2   = (const float*)d_in[17];
    float* out = (float*)d_out;

    const int LAYER_SMEM = 195712;
    const int PRO_SMEM   = 32768 + 22528 + 1024;  // 56320 B
    cudaFuncSetAttribute(layer_kernel,    cudaFuncAttributeMaxDynamicSharedMemorySize, LAYER_SMEM);
    cudaFuncSetAttribute(prologue_kernel, cudaFuncAttributeMaxDynamicSharedMemorySize, PRO_SMEM);

    cudaMemsetAsync(d_out, 0, (size_t)out_size * sizeof(float), 0);
    prologue_kernel<<<36, 1024, PRO_SMEM>>>(attention);
    sortgather_kernel<<<2, 256>>>(x_skip);
    pos_kernel<<<2048, 256>>>();

    // qkv for layer 0 only
    layer_kernel<<<dim3(64, 2), 512, LAYER_SMEM>>>(
        Wo, bo, ln2g, ln2b, W1, b1, W2, b2,
        ln1g, ln1b, Wq, Wk, Wv, Wrel, rcb, rpb, out,
        0, 0, /*do_am=*/0, /*do_qkv=*/1);

    for (int l = 0; l < 4; l++) {
        layer_kernel<<<dim3(64, 2), 512, LAYER_SMEM>>>(
            Wo, bo, ln2g, ln2b, W1, b1, W2, b2,
            ln1g, ln1b, Wq, Wk, Wv, Wrel, rcb, rpb, out,
            l, (l < 3) ? (l + 1) : 0, /*do_am=*/1, /*do_qkv=*/(l < 3) ? 1 : 0);
    }
}

// round 13
// speedup vs baseline: 1.2766x; 1.2766x over previous
#include <cuda_runtime.h>
#include <cuda_fp16.h>
#include <math.h>

#define LSEQ 45000

// ---------------- device scratch (no allocs allowed) ----------------
__device__ uint4 d_posh4[1048576];          // [2][512][512] * 32B (16 halfs: 15 feats + sign)
__device__ int   d_topk[2][2][256];
__device__ int   d_idxg[2][512];
__device__ float d_emb[2*512*32];
__device__ __align__(16) __half d_kkh[2*4*32*512];   // [b*4+h][d][j] fp16
__device__ __align__(16) __half d_vvh[2*4*32*512];
__device__ float d_qcb[2*4*512*32];         // q*scale + rcb   [bh][i][d]
__device__ float d_qrl[2*512*4*32];         // [b][i][h][30 used]
__device__ float d_att[2*512*128];          // attention output pre-Wo
__device__ float d_cc[24];                  // 0..4 c1, 5..9 lz, 10..14 rate, 15..19 conc-1
__device__ int   d_pmaxbits;                // global gamma max (positive-float bits)

__device__ __forceinline__ __half2 u2h(unsigned u) { return *reinterpret_cast<__half2*>(&u); }
__device__ __forceinline__ unsigned h2u(__half2 h) { return *reinterpret_cast<unsigned*>(&h); }

// ---------------- no-op: shifts ncu -s window so attn gets profiled ----------------
__global__ void nudge_kernel() {}

// ---------------- prologue: blocks 0-3 top-256 select, blocks 4-35 basis setup ----------------
#define TK_CAP 2816
__global__ void __launch_bounds__(1024) prologue_kernel(const float* __restrict__ att) {
    extern __shared__ unsigned char tks[];
    int t = threadIdx.x, lane = t & 31;

    if (blockIdx.x >= 4) {
        float* red = (float*)tks;
        int bid = blockIdx.x - 4;
        double L2S = log(45000.0) / log(2.0);
        float c1[5], lz[5], rate[5], cm1[5];
        for (int k = 0; k < 5; k++) {
            double lin = 3.0 + (L2S - 3.0) * ((double)k / 4.0);
            float hl = (float)exp2(lin);
            c1[k] = -0.69314718055994531f / hl;
            double mean = 9000.0 * (k + 1);
            double sd = 4500.0;
            float conc = (float)((mean / sd) * (mean / sd));
            float rt = (float)(mean / (sd * sd));
            rate[k] = rt; cm1[k] = conc - 1.0f;
            lz[k] = lgammaf(conc) - conc * logf(rt);
        }
        float m = 1e-8f;
        for (int a_ = bid * 1024 + t; a_ < LSEQ; a_ += 32768) {
            if (a_ == 0) continue;
            float a = (float)a_;
            float la = logf(a);
            for (int k = 0; k < 5; k++) {
                float p = expf(cm1[k] * la - rate[k] * a - lz[k]) + 1e-8f;
                m = fmaxf(m, p);
            }
        }
        red[t] = m; __syncthreads();
        for (int s = 512; s > 0; s >>= 1) {
            if (t < s) red[t] = fmaxf(red[t], red[t + s]);
            __syncthreads();
        }
        if (t == 0) atomicMax(&d_pmaxbits, __float_as_int(red[0]));
        if (bid == 0 && t == 0) {
            for (int k = 0; k < 5; k++) { d_cc[k] = c1[k]; d_cc[5+k] = lz[k]; d_cc[10+k] = rate[k]; d_cc[15+k] = cm1[k]; }
        }
        return;
    }

    unsigned* hist = (unsigned*)tks;                                     // 8192 u
    unsigned long long* cand = (unsigned long long*)(tks + 32768);       // 2816
    unsigned* ps = (unsigned*)(tks + 32768 + 22528);                     // 256
    __shared__ unsigned thrT;
    __shared__ int cnt, ocnt, rem_s;
    __shared__ unsigned long long pref_s;
    int b = blockIdx.x >> 1, ch = (blockIdx.x & 1) + 1;
    const float* vals = att + (size_t)(b * 3 + ch) * LSEQ;
    for (int i = t; i < 8192; i += 1024) hist[i] = 0;
    if (t == 0) { cnt = 0; ocnt = 0; pref_s = 0ull; rem_s = 256; }
    __syncthreads();
    for (int j = t; j < LSEQ; j += 1024) {
        unsigned u = __float_as_uint(vals[j]);
        u = (u & 0x80000000u) ? ~u : (u | 0x80000000u);
        atomicAdd(&hist[u >> 19], 1u);
    }
    __syncthreads();
    if (t < 256) {
        unsigned sum = 0;
        int base = 8191 - t * 32;
        for (int k = 0; k < 32; k++) sum += hist[base - k];
        ps[t] = sum;
    }
    __syncthreads();
    if (t < 32) {
        unsigned s = 0;
        #pragma unroll
        for (int k = 0; k < 8; k++) s += ps[lane * 8 + k];
        unsigned pre = s;
        #pragma unroll
        for (int o = 1; o < 32; o <<= 1) { unsigned v = __shfl_up_sync(0xffffffffu, pre, o); if (lane >= o) pre += v; }
        bool hit = (pre >= 256u) && (pre - s) < 256u;
        unsigned mk = __ballot_sync(0xffffffffu, hit);
        if (lane == (__ffs(mk) - 1)) {
            unsigned cum = pre - s;
            int T = 0;
            for (int k = 0; k < 8; k++) {
                int ci = lane * 8 + k;
                if (cum + ps[ci] >= 256u) {
                    int base = 8191 - ci * 32;
                    for (int kk = 0; kk < 32; kk++) { cum += hist[base - kk]; if (cum >= 256u) { T = base - kk; break; } }
                    break;
                }
                cum += ps[ci];
            }
            thrT = (unsigned)T;
        }
    }
    __syncthreads();
    unsigned T = thrT;
    for (int j = t; j < LSEQ; j += 1024) {
        unsigned u = __float_as_uint(vals[j]);
        u = (u & 0x80000000u) ? ~u : (u | 0x80000000u);
        if ((u >> 19) >= T) {
            int pi = atomicAdd(&cnt, 1);
            if (pi < TK_CAP) cand[pi] = (((unsigned long long)u) << 32) | (unsigned)(0xFFFFFFFFu - (unsigned)j);
        }
    }
    __syncthreads();
    int n = cnt < TK_CAP ? cnt : TK_CAP;
    for (int shift = 56; shift >= 0; shift -= 8) {
        if (t < 256) hist[t] = 0;
        __syncthreads();
        unsigned long long p = pref_s;
        unsigned long long mh = (shift == 56) ? 0ull : ~((1ull << (shift + 8)) - 1ull);
        for (int i = t; i < n; i += 1024) {
            unsigned long long k = cand[i];
            if ((k & mh) == p) atomicAdd(&hist[(unsigned)(k >> shift) & 255u], 1u);
        }
        __syncthreads();
        if (t < 32) {
            int r = rem_s;
            unsigned s = 0;
            #pragma unroll
            for (int k = 0; k < 8; k++) s += hist[255 - (lane * 8 + k)];
            unsigned pre = s;
            #pragma unroll
            for (int o = 1; o < 32; o <<= 1) { unsigned v = __shfl_up_sync(0xffffffffu, pre, o); if (lane >= o) pre += v; }
            bool hit = ((int)pre >= r) && (int)(pre - s) < r;
            unsigned mk = __ballot_sync(0xffffffffu, hit);
            if (lane == (__ffs(mk) - 1)) {
                unsigned cum = pre - s;
                for (int k = 0; k < 8; k++) {
                    int bin = 255 - (lane * 8 + k);
                    cum += hist[bin];
                    if ((int)cum >= r) { rem_s = r - (int)(cum - hist[bin]); pref_s = p | ((unsigned long long)bin << shift); break; }
                }
            }
        }
        __syncthreads();
    }
    unsigned long long kth = pref_s;
    for (int i = t; i < n; i += 1024) {
        if (cand[i] >= kth) {
            int pi = atomicAdd(&ocnt, 1);
            if (pi < 256) d_topk[b][ch - 1][pi] = (int)(0xFFFFFFFFu - (unsigned)(cand[i] & 0xFFFFFFFFull));
        }
    }
}

// ---------------- merge+sort 512 indices, gather embeddings ----------------
__global__ void __launch_bounds__(256) sortgather_kernel(const float* __restrict__ x_skip) {
    int b = blockIdx.x, t = threadIdx.x;
    __shared__ int s[512];
    s[t] = d_topk[b][0][t];
    s[256 + t] = d_topk[b][1][t];
    __syncthreads();
    for (int k = 2; k <= 512; k <<= 1) {
        for (int j = k >> 1; j > 0; j >>= 1) {
            #pragma unroll
            for (int half = 0; half < 2; half++) {
                int idx = half * 256 + t;
                int ixj = idx ^ j;
                if (ixj > idx) {
                    int a = s[idx], c = s[ixj];
                    bool up = ((idx & k) == 0);
                    if ((a > c) == up) { s[idx] = c; s[ixj] = a; }
                }
            }
            __syncthreads();
        }
    }
    d_idxg[b][t] = s[t];
    d_idxg[b][256 + t] = s[256 + t];
    __syncthreads();
    for (int q = t; q < 512 * 32; q += 256) {
        int i = q >> 5, c = q & 31;
        d_emb[(b * 512 + i) * 32 + c] = x_skip[((size_t)b * 32 + c) * LSEQ + s[i]];
    }
}

// ---------------- positional basis features (layer-invariant, fp16 packed) ----------------
__global__ void __launch_bounds__(256) pos_kernel() {
    unsigned int id = blockIdx.x * 256u + threadIdx.x;   // 2*512*512 threads
    int b = id >> 18;
    unsigned int r = id & 262143u;
    int i = r >> 9, j = r & 511;
    int d = d_idxg[b][i] - d_idxg[b][j];
    float a = fabsf((float)d);
    float sg = (d > 0) ? 1.f : ((d < 0) ? -1.f : 0.f);
    float f[16];
    #pragma unroll
    for (int k = 0; k < 5; k++) f[k] = expf(d_cc[k] * a);
    f[5] = (1.f  > a) ? 1.f : 0.f;
    f[6] = (3.f  > a) ? 1.f : 0.f;
    f[7] = (7.f  > a) ? 1.f : 0.f;
    f[8] = (15.f > a) ? 1.f : 0.f;
    f[9] = (31.f > a) ? 1.f : 0.f;
    float la = logf(a);                 // a==0 -> -inf -> exp -> 0 (matches xlogy path)
    float invp = 1.0f / __int_as_float(d_pmaxbits);
    #pragma unroll
    for (int k = 0; k < 5; k++) {
        float lp = d_cc[15 + k] * la - d_cc[10 + k] * a;
        f[10 + k] = (expf(lp - d_cc[5 + k]) + 1e-8f) * invp;
    }
    f[15] = sg;
    unsigned u[8];
    #pragma unroll
    for (int k = 0; k < 8; k++) u[k] = h2u(__floats2half2_rn(f[2 * k], f[2 * k + 1]));
    uint4* o = d_posh4 + (size_t)id * 2u;
    o[0] = make_uint4(u[0], u[1], u[2], u[3]);
    o[1] = make_uint4(u[4], u[5], u[6], u[7]);
}

// ---------------- attention: 16 rows/block, 2 rows/warp, coalesced j-mapping ----------------
// lane owns j = ch*128 + u*32 + lane  (pos LDG stride 32B/lane -> 8 lines/instr, was 32)
__global__ void __launch_bounds__(256, 2) attn_kernel() {
    extern __shared__ __align__(16) unsigned char smraw[];
    __half* Kh = (__half*)smraw;                       // 32KB [d][j]
    __half* Vh = (__half*)(smraw + 32768);             // 32KB
    float* qcs = (float*)(smraw + 65536);              // 512 f
    unsigned* qAh = (unsigned*)(smraw + 67584);        // 128 u
    unsigned* qBh = (unsigned*)(smraw + 68096);        // 128 u
    int t = threadIdx.x, lane = t & 31, w = t >> 5;
    int i0 = blockIdx.x * 16;
    int hd = blockIdx.y;
    int b = blockIdx.z;
    int bh = b * 4 + hd;

    {
        const uint4* kg = (const uint4*)(d_kkh + bh * 16384);
        const uint4* vg = (const uint4*)(d_vvh + bh * 16384);
        uint4* ks4 = (uint4*)Kh; uint4* vs4 = (uint4*)Vh;
        for (int q = t; q < 2048; q += 256) { ks4[q] = kg[q]; vs4[q] = vg[q]; }
    }
    for (int q = t; q < 512; q += 256)
        qcs[q] = d_qcb[(bh * 512 + i0 + (q >> 5)) * 32 + (q & 31)];
    if (t < 128) {
        int r = t >> 3, p = t & 7;
        const float* qr = d_qrl + (((b * 512) + i0 + r) * 4 + hd) * 32;
        int f0 = 2 * p, f1 = f0 + 1;
        float a0 = qr[f0],      a1 = (f1 < 15) ? qr[f1] : 0.f;
        float b0 = qr[15 + f0], b1 = (f1 < 15) ? qr[15 + f1] : 0.f;
        qAh[r * 8 + p] = h2u(__floats2half2_rn(a0, a1));
        qBh[r * 8 + p] = h2u(__floats2half2_rn(b0, b1));
    }
    __syncthreads();

    int r0 = 2 * w, r1 = r0 + 1;
    float s0[16], s1[16];
    #pragma unroll
    for (int q = 0; q < 16; q++) { s0[q] = 0.f; s1[q] = 0.f; }

    // content QK: scalar LDS.16, j = ch*128 + u*32 + lane
    for (int d = 0; d < 32; d++) {
        float qv0 = qcs[r0 * 32 + d], qv1 = qcs[r1 * 32 + d];
        const __half* kr = Kh + d * 512;
        #pragma unroll
        for (int ch = 0; ch < 4; ch++) {
            #pragma unroll
            for (int u = 0; u < 4; u++) {
                float kv = __half2float(kr[ch * 128 + u * 32 + lane]);
                s0[ch * 4 + u] += qv0 * kv;
                s1[ch * 4 + u] += qv1 * kv;
            }
        }
    }

    // rel: coalesced pos loads
    {
        __half2 qa0[8], qb0[8], qa1[8], qb1[8];
        #pragma unroll
        for (int p = 0; p < 8; p++) {
            qa0[p] = u2h(qAh[r0 * 8 + p]); qb0[p] = u2h(qBh[r0 * 8 + p]);
            qa1[p] = u2h(qAh[r1 * 8 + p]); qb1[p] = u2h(qBh[r1 * 8 + p]);
        }
        const uint4* prow0 = d_posh4 + 2 * (size_t)((b * 512 + i0 + r0) * 512);
        const uint4* prow1 = d_posh4 + 2 * (size_t)((b * 512 + i0 + r1) * 512);
        #pragma unroll
        for (int ch = 0; ch < 4; ch++) {
            #pragma unroll
            for (int u = 0; u < 4; u++) {
                int j = ch * 128 + u * 32 + lane;
                {
                    uint4 A = prow0[2 * j], B = prow0[2 * j + 1];
                    __half2 sA = __hmul2(u2h(A.x), qa0[0]);
                    sA = __hfma2(u2h(A.y), qa0[1], sA); sA = __hfma2(u2h(A.z), qa0[2], sA);
                    sA = __hfma2(u2h(A.w), qa0[3], sA); sA = __hfma2(u2h(B.x), qa0[4], sA);
                    sA = __hfma2(u2h(B.y), qa0[5], sA); sA = __hfma2(u2h(B.z), qa0[6], sA);
                    sA = __hfma2(u2h(B.w), qa0[7], sA);
                    __half2 sB = __hmul2(u2h(A.x), qb0[0]);
                    sB = __hfma2(u2h(A.y), qb0[1], sB); sB = __hfma2(u2h(A.z), qb0[2], sB);
                    sB = __hfma2(u2h(A.w), qb0[3], sB); sB = __hfma2(u2h(B.x), qb0[4], sB);
                    sB = __hfma2(u2h(B.y), qb0[5], sB); sB = __hfma2(u2h(B.z), qb0[6], sB);
                    sB = __hfma2(u2h(B.w), qb0[7], sB);
                    float2 fA = __half22float2(sA), fB = __half22float2(sB);
                    float sg = __high2float(u2h(B.w));
                    s0[ch * 4 + u] += (fA.x + fA.y) + sg * (fB.x + fB.y);
                }
                {
                    uint4 A = prow1[2 * j], B = prow1[2 * j + 1];
                    __half2 sA = __hmul2(u2h(A.x), qa1[0]);
                    sA = __hfma2(u2h(A.y), qa1[1], sA); sA = __hfma2(u2h(A.z), qa1[2], sA);
                    sA = __hfma2(u2h(A.w), qa1[3], sA); sA = __hfma2(u2h(B.x), qa1[4], sA);
                    sA = __hfma2(u2h(B.y), qa1[5], sA); sA = __hfma2(u2h(B.z), qa1[6], sA);
                    sA = __hfma2(u2h(B.w), qa1[7], sA);
                    __half2 sB = __hmul2(u2h(A.x), qb1[0]);
                    sB = __hfma2(u2h(A.y), qb1[1], sB); sB = __hfma2(u2h(A.z), qb1[2], sB);
                    sB = __hfma2(u2h(A.w), qb1[3], sB); sB = __hfma2(u2h(B.x), qb1[4], sB);
                    sB = __hfma2(u2h(B.y), qb1[5], sB); sB = __hfma2(u2h(B.z), qb1[6], sB);
                    sB = __hfma2(u2h(B.w), qb1[7], sB);
                    float2 fA = __half22float2(sA), fB = __half22float2(sB);
                    float sg = __high2float(u2h(B.w));
                    s1[ch * 4 + u] += (fA.x + fA.y) + sg * (fB.x + fB.y);
                }
            }
        }
    }

    float m0 = -3.0e38f, m1 = -3.0e38f;
    #pragma unroll
    for (int q = 0; q < 16; q++) { m0 = fmaxf(m0, s0[q]); m1 = fmaxf(m1, s1[q]); }
    #pragma unroll
    for (int o = 16; o > 0; o >>= 1) {
        m0 = fmaxf(m0, __shfl_xor_sync(0xffffffffu, m0, o));
        m1 = fmaxf(m1, __shfl_xor_sync(0xffffffffu, m1, o));
    }
    float su0 = 0.f, su1 = 0.f;
    #pragma unroll
    for (int q = 0; q < 16; q++) {
        s0[q] = expf(s0[q] - m0); su0 += s0[q];
        s1[q] = expf(s1[q] - m1); su1 += s1[q];
    }
    #pragma unroll
    for (int o = 16; o > 0; o >>= 1) {
        su0 += __shfl_xor_sync(0xffffffffu, su0, o);
        su1 += __shfl_xor_sync(0xffffffffu, su1, o);
    }
    float inv0 = 1.f / su0, inv1 = 1.f / su1;

    // PV in two d-halves; scalar V loads with same j-mapping; butterfly transpose-reduce
    #pragma unroll
    for (int pass = 0; pass < 2; pass++) {
        float v[32];
        #pragma unroll
        for (int k = 0; k < 16; k++) {
            int d = pass * 16 + k;
            const __half* vr = Vh + d * 512;
            float a0 = 0.f, a1 = 0.f;
            #pragma unroll
            for (int ch = 0; ch < 4; ch++) {
                #pragma unroll
                for (int u = 0; u < 4; u++) {
                    float vv = __half2float(vr[ch * 128 + u * 32 + lane]);
                    a0 += s0[ch * 4 + u] * vv;
                    a1 += s1[ch * 4 + u] * vv;
                }
            }
            v[k] = a0; v[16 + k] = a1;
        }
        #pragma unroll
        for (int m = 16; m >= 1; m >>= 1) {
            #pragma unroll
            for (int k = 0; k < m; k++) {
                float give = (lane & m) ? v[k] : v[k + m];
                float got = __shfl_xor_sync(0xffffffffu, give, m);
                v[k] = (lane & m) ? (v[k + m] + got) : (v[k] + got);
            }
        }
        float outv = v[0] * ((lane < 16) ? inv0 : inv1);
        int row = (lane < 16) ? r0 : r1;
        int dd = (lane & 15) + pass * 16;
        d_att[(b * 512 + i0 + row) * 128 + hd * 32 + dd] = outv;
    }
}

// ---------------- fused: [mlp lm] + [qkv lq], 8 tokens/block, 512 threads (R8-exact) ----------------
__global__ void __launch_bounds__(512, 1) fused_kernel(
    const float* __restrict__ Wo, const float* __restrict__ bo,
    const float* __restrict__ ln2g, const float* __restrict__ ln2b,
    const float* __restrict__ W1, const float* __restrict__ b1,
    const float* __restrict__ W2, const float* __restrict__ b2,
    const float* __restrict__ ln1g, const float* __restrict__ ln1b,
    const float* __restrict__ Wq, const float* __restrict__ Wk, const float* __restrict__ Wv,
    const float* __restrict__ Wrel, const float* __restrict__ rcb, const float* __restrict__ rpb,
    int lm, int lq, int do_mlp, int do_qkv)
{
    extern __shared__ float sm[];
    float* ats = sm;                  // 1024
    float* es  = sm + 1024;           // 256
    float* h2s = sm + 1280;           // 256
    float* tbs = sm + 1536;           // 4096
    float* red = sm + 5632;           // 4096
    float* qp  = sm + 9728;           // 1024
    float* Wrs = sm + 10752;          // 3870 -> 14622 floats total
    int t = threadIdx.x, lane = t & 31, w = t >> 5;
    int i0 = blockIdx.x * 8, b = blockIdx.y;

    if (do_qkv) {
        for (int q = t; q < 3840; q += 512) {
            int f = q >> 7, c = q & 127;
            Wrs[f * 129 + c] = Wrel[lq * 3840 + q];
        }
    }

    if (do_mlp) {
        for (int q = t; q < 1024; q += 512) ats[q] = d_att[(b * 512 + i0) * 128 + q];
        __syncthreads();
        {
            int oi = t >> 1, hf = t & 1;
            int tok = oi >> 5, c = oi & 31;
            const float* wo = Wo + lm * 4096;
            int mb = hf * 64;
            float acc = 0.f;
            #pragma unroll 16
            for (int m = 0; m < 64; m++) acc += ats[tok * 128 + mb + m] * wo[(mb + m) * 32 + c];
            acc += __shfl_xor_sync(0xffffffffu, acc, 1);
            if (hf == 0) es[oi] = d_emb[(b * 512 + i0 + tok) * 32 + c] + acc + bo[lm * 32 + c];
        }
        __syncthreads();
        if (w < 8) {
            float x = es[w * 32 + lane];
            float s1 = x;
            #pragma unroll
            for (int o = 16; o > 0; o >>= 1) s1 += __shfl_xor_sync(0xffffffffu, s1, o);
            float mu = s1 * (1.f / 32.f);
            float dd = x - mu;
            float s2 = dd * dd;
            #pragma unroll
            for (int o = 16; o > 0; o >>= 1) s2 += __shfl_xor_sync(0xffffffffu, s2, o);
            float rs = rsqrtf(s2 * (1.f / 32.f) + 1e-5f);
            h2s[w * 32 + lane] = dd * rs * ln2g[lm * 32 + lane] + ln2b[lm * 32 + lane];
        }
        __syncthreads();
        {
            int m = t;
            const float* w1 = W1 + lm * 16384;
            float wcol[32];
            #pragma unroll
            for (int cc = 0; cc < 32; cc++) wcol[cc] = w1[cc * 512 + m];
            float bb = b1[lm * 512 + m];
            #pragma unroll
            for (int tok = 0; tok < 8; tok++) {
                float s = bb;
                #pragma unroll
                for (int cc = 0; cc < 32; cc++) s += h2s[tok * 32 + cc] * wcol[cc];
                tbs[tok * 512 + m] = 0.5f * s * (1.f + erff(s * 0.70710678118654752f));
            }
        }
        __syncthreads();
        {
            const float* w2 = W2 + lm * 16384;
            int m0 = w * 32;
            float accw[8];
            #pragma unroll
            for (int tok = 0; tok < 8; tok++) accw[tok] = 0.f;
            #pragma unroll 4
            for (int mm = 0; mm < 32; mm++) {
                float w2v = w2[(m0 + mm) * 32 + lane];
                #pragma unroll
                for (int tok = 0; tok < 8; tok++) accw[tok] += tbs[tok * 512 + m0 + mm] * w2v;
            }
            #pragma unroll
            for (int tok = 0; tok < 8; tok++) red[(w * 8 + tok) * 32 + lane] = accw[tok];
        }
        __syncthreads();
        if (t < 256) {
            int tok = t >> 5, c = t & 31;
            float s = 0.f;
            #pragma unroll
            for (int ww = 0; ww < 16; ww++) s += red[(ww * 8 + tok) * 32 + c];
            float ne = es[t] + s + b2[lm * 32 + c];
            d_emb[(b * 512 + i0 + tok) * 32 + c] = ne;
            es[t] = ne;
        }
    } else {
        if (t < 256) es[t] = d_emb[(b * 512 + i0) * 32 + t];
    }
    __syncthreads();

    if (!do_qkv) return;

    if (w < 8) {
        float x = es[w * 32 + lane];
        float s1 = x;
        #pragma unroll
        for (int o = 16; o > 0; o >>= 1) s1 += __shfl_xor_sync(0xffffffffu, s1, o);
        float mu = s1 * (1.f / 32.f);
        float dd = x - mu;
        float s2 = dd * dd;
        #pragma unroll
        for (int o = 16; o > 0; o >>= 1) s2 += __shfl_xor_sync(0xffffffffu, s2, o);
        float rs = rsqrtf(s2 * (1.f / 32.f) + 1e-5f);
        h2s[w * 32 + lane] = dd * rs * ln1g[lq * 32 + lane] + ln1b[lq * 32 + lane];
    }
    __syncthreads();
    {
        int c = t & 127, tg = t >> 7;
        int hh = c >> 5, dd = c & 31;
        int bh = b * 4 + hh;
        float rc = rcb[(lq * 4 + hh) * 32 + dd];
        float rp = rpb[(lq * 4 + hh) * 32 + dd];
        const float* wq = Wq + lq * 4096;
        const float* wk = Wk + lq * 4096;
        const float* wv = Wv + lq * 4096;
        float accq[2] = {0.f, 0.f}, acck[2] = {0.f, 0.f}, accv[2] = {0.f, 0.f};
        #pragma unroll 8
        for (int cc = 0; cc < 32; cc++) {
            float a = wq[cc * 128 + c], kwe = wk[cc * 128 + c], vwe = wv[cc * 128 + c];
            #pragma unroll
            for (int tk = 0; tk < 2; tk++) {
                float hc = h2s[(tg * 2 + tk) * 32 + cc];
                accq[tk] += hc * a; acck[tk] += hc * kwe; accv[tk] += hc * vwe;
            }
        }
        #pragma unroll
        for (int tk = 0; tk < 2; tk++) {
            int tok = tg * 2 + tk;
            float q = accq[tk] * 0.17677669529663687f;
            d_qcb[(bh * 512 + i0 + tok) * 32 + dd] = q + rc;
            qp[tok * 128 + c] = q + rp;
        }
        *(unsigned*)&d_kkh[(bh * 32 + dd) * 512 + i0 + tg * 2] = h2u(__floats2half2_rn(acck[0], acck[1]));
        *(unsigned*)&d_vvh[(bh * 32 + dd) * 512 + i0 + tg * 2] = h2u(__floats2half2_rn(accv[0], accv[1]));
    }
    __syncthreads();
    if (lane < 30) {
        int f = lane, tok = w >> 1, h2b = (w & 1) * 2;
        #pragma unroll
        for (int k = 0; k < 2; k++) {
            int hh2 = h2b + k;
            float s = 0.f;
            #pragma unroll
            for (int d2 = 0; d2 < 32; d2++)
                s += Wrs[f * 129 + hh2 * 32 + d2] * qp[tok * 128 + hh2 * 32 + d2];
            d_qrl[((b * 512 + i0 + tok) * 4 + hh2) * 32 + f] = s;
        }
    }
}

// ---------------- scatter back into [B,C,L] ----------------
__global__ void scatter_kernel(float* __restrict__ out) {
    int i = blockIdx.x, b = blockIdx.y, c = threadIdx.x;
    out[((size_t)b * 32 + c) * LSEQ + d_idxg[b][i]] = d_emb[(b * 512 + i) * 32 + c];
}

// ---------------- launch ----------------
extern "C" void kernel_launch(void* const* d_in, const int* in_sizes, int n_in,
                              void* d_out, int out_size) {
    (void)in_sizes; (void)n_in;
    const float* x_skip    = (const float*)d_in[0];
    const float* attention = (const float*)d_in[1];
    const float* ln1g = (const float*)d_in[2];
    const float* ln1b = (const float*)d_in[3];
    const float* Wq   = (const float*)d_in[4];
    const float* Wk   = (const float*)d_in[5];
    const float* Wv   = (const float*)d_in[6];
    const float* Wrel = (const float*)d_in[7];
    const float* rcb  = (const float*)d_in[8];
    const float* rpb  = (const float*)d_in[9];
    const float* Wo   = (const float*)d_in[10];
    const float* bo   = (const float*)d_in[11];
    const float* ln2g = (const float*)d_in[12];
    const float* ln2b = (const float*)d_in[13];
    const float* W1   = (const float*)d_in[14];
    const float* b1   = (const float*)d_in[15];
    const float* W2   = (const float*)d_in[16];
    const float* b2   = (const float*)d_in[17];
    float* out = (float*)d_out;

    const int ATT_SMEM   = 68608;
    const int FUSED_SMEM = 14622 * 4;             // 58488 B
    const int PRO_SMEM   = 32768 + 22528 + 1024;  // 56320 B
    cudaFuncSetAttribute(attn_kernel,     cudaFuncAttributeMaxDynamicSharedMemorySize, ATT_SMEM);
    cudaFuncSetAttribute(fused_kernel,    cudaFuncAttributeMaxDynamicSharedMemorySize, FUSED_SMEM);
    cudaFuncSetAttribute(prologue_kernel, cudaFuncAttributeMaxDynamicSharedMemorySize, PRO_SMEM);

    cudaMemsetAsync(d_out, 0, (size_t)out_size * sizeof(float), 0);
    nudge_kernel<<<1, 32>>>();   // shifts ncu -s window so attn is profiled
    prologue_kernel<<<36, 1024, PRO_SMEM>>>(attention);
    sortgather_kernel<<<2, 256>>>(x_skip);
    pos_kernel<<<2048, 256>>>();

    // qkv for layer 0
    fused_kernel<<<dim3(64, 2), 512, FUSED_SMEM>>>(
        Wo, bo, ln2g, ln2b, W1, b1, W2, b2,
        ln1g, ln1b, Wq, Wk, Wv, Wrel, rcb, rpb,
        0, 0, /*do_mlp=*/0, /*do_qkv=*/1);

    for (int l = 0; l < 4; l++) {
        attn_kernel<<<dim3(32, 4, 2), 256, ATT_SMEM>>>();
        fused_kernel<<<dim3(64, 2), 512, FUSED_SMEM>>>(
            Wo, bo, ln2g, ln2b, W1, b1, W2, b2,
            ln1g, ln1b, Wq, Wk, Wv, Wrel, rcb, rpb,
            l, l + 1, /*do_mlp=*/1, /*do_qkv=*/(l < 3) ? 1 : 0);
    }

    scatter_kernel<<<dim3(512, 2), 32>>>(out);
}

// round 14
// speedup vs baseline: 1.2860x; 1.0073x over previous
#include <cuda_runtime.h>
#include <cuda_fp16.h>
#include <math.h>

#define LSEQ 45000

// ---------------- device scratch (no allocs allowed) ----------------
__device__ uint4 d_posh4[1048576];          // [2][512][512] * 32B (16 halfs: 15 feats + sign)
__device__ int   d_topk[2][2][256];
__device__ int   d_idxg[2][512];
__device__ float d_emb[2*512*32];
__device__ __align__(16) __half d_kkh[2*4*32*512];   // [b*4+h][d][j] fp16
__device__ __align__(16) __half d_vvh[2*4*32*512];
__device__ float d_qcb[2*4*512*32];         // q*scale + rcb   [bh][i][d]
__device__ float d_qrl[2*512*4*32];         // [b][i][h][30 used]
__device__ float d_att[2*512*128];          // attention output pre-Wo
__device__ float d_cc[24];                  // 0..4 c1, 5..9 lz, 10..14 rate, 15..19 conc-1
__device__ int   d_pmaxbits;                // global gamma max (positive-float bits)

__device__ __forceinline__ __half2 u2h(unsigned u) { return *reinterpret_cast<__half2*>(&u); }
__device__ __forceinline__ unsigned h2u(__half2 h) { return *reinterpret_cast<unsigned*>(&h); }

// ---------------- prologue: blocks 0-3 top-256 select, blocks 4-35 basis setup ----------------
#define TK_CAP 2816
__global__ void __launch_bounds__(1024) prologue_kernel(const float* __restrict__ att) {
    extern __shared__ unsigned char tks[];
    int t = threadIdx.x, lane = t & 31;

    if (blockIdx.x >= 4) {
        float* red = (float*)tks;
        int bid = blockIdx.x - 4;
        double L2S = log(45000.0) / log(2.0);
        float c1[5], lz[5], rate[5], cm1[5];
        for (int k = 0; k < 5; k++) {
            double lin = 3.0 + (L2S - 3.0) * ((double)k / 4.0);
            float hl = (float)exp2(lin);
            c1[k] = -0.69314718055994531f / hl;
            double mean = 9000.0 * (k + 1);
            double sd = 4500.0;
            float conc = (float)((mean / sd) * (mean / sd));
            float rt = (float)(mean / (sd * sd));
            rate[k] = rt; cm1[k] = conc - 1.0f;
            lz[k] = lgammaf(conc) - conc * logf(rt);
        }
        float m = 1e-8f;
        for (int a_ = bid * 1024 + t; a_ < LSEQ; a_ += 32768) {
            if (a_ == 0) continue;
            float a = (float)a_;
            float la = logf(a);
            for (int k = 0; k < 5; k++) {
                float p = expf(cm1[k] * la - rate[k] * a - lz[k]) + 1e-8f;
                m = fmaxf(m, p);
            }
        }
        red[t] = m; __syncthreads();
        for (int s = 512; s > 0; s >>= 1) {
            if (t < s) red[t] = fmaxf(red[t], red[t + s]);
            __syncthreads();
        }
        if (t == 0) atomicMax(&d_pmaxbits, __float_as_int(red[0]));
        if (bid == 0 && t == 0) {
            for (int k = 0; k < 5; k++) { d_cc[k] = c1[k]; d_cc[5+k] = lz[k]; d_cc[10+k] = rate[k]; d_cc[15+k] = cm1[k]; }
        }
        return;
    }

    unsigned* hist = (unsigned*)tks;                                     // 8192 u
    unsigned long long* cand = (unsigned long long*)(tks + 32768);       // 2816
    unsigned* ps = (unsigned*)(tks + 32768 + 22528);                     // 256
    __shared__ unsigned thrT;
    __shared__ int cnt, ocnt, rem_s;
    __shared__ unsigned long long pref_s;
    int b = blockIdx.x >> 1, ch = (blockIdx.x & 1) + 1;
    const float* vals = att + (size_t)(b * 3 + ch) * LSEQ;
    for (int i = t; i < 8192; i += 1024) hist[i] = 0;
    if (t == 0) { cnt = 0; ocnt = 0; pref_s = 0ull; rem_s = 256; }
    __syncthreads();
    for (int j = t; j < LSEQ; j += 1024) {
        unsigned u = __float_as_uint(vals[j]);
        u = (u & 0x80000000u) ? ~u : (u | 0x80000000u);
        atomicAdd(&hist[u >> 19], 1u);
    }
    __syncthreads();
    if (t < 256) {
        unsigned sum = 0;
        int base = 8191 - t * 32;
        for (int k = 0; k < 32; k++) sum += hist[base - k];
        ps[t] = sum;
    }
    __syncthreads();
    if (t < 32) {
        unsigned s = 0;
        #pragma unroll
        for (int k = 0; k < 8; k++) s += ps[lane * 8 + k];
        unsigned pre = s;
        #pragma unroll
        for (int o = 1; o < 32; o <<= 1) { unsigned v = __shfl_up_sync(0xffffffffu, pre, o); if (lane >= o) pre += v; }
        bool hit = (pre >= 256u) && (pre - s) < 256u;
        unsigned mk = __ballot_sync(0xffffffffu, hit);
        if (lane == (__ffs(mk) - 1)) {
            unsigned cum = pre - s;
            int T = 0;
            for (int k = 0; k < 8; k++) {
                int ci = lane * 8 + k;
                if (cum + ps[ci] >= 256u) {
                    int base = 8191 - ci * 32;
                    for (int kk = 0; kk < 32; kk++) { cum += hist[base - kk]; if (cum >= 256u) { T = base - kk; break; } }
                    break;
                }
                cum += ps[ci];
            }
            thrT = (unsigned)T;
        }
    }
    __syncthreads();
    unsigned T = thrT;
    for (int j = t; j < LSEQ; j += 1024) {
        unsigned u = __float_as_uint(vals[j]);
        u = (u & 0x80000000u) ? ~u : (u | 0x80000000u);
        if ((u >> 19) >= T) {
            int pi = atomicAdd(&cnt, 1);
            if (pi < TK_CAP) cand[pi] = (((unsigned long long)u) << 32) | (unsigned)(0xFFFFFFFFu - (unsigned)j);
        }
    }
    __syncthreads();
    int n = cnt < TK_CAP ? cnt : TK_CAP;
    for (int shift = 56; shift >= 0; shift -= 8) {
        if (t < 256) hist[t] = 0;
        __syncthreads();
        unsigned long long p = pref_s;
        unsigned long long mh = (shift == 56) ? 0ull : ~((1ull << (shift + 8)) - 1ull);
        for (int i = t; i < n; i += 1024) {
            unsigned long long k = cand[i];
            if ((k & mh) == p) atomicAdd(&hist[(unsigned)(k >> shift) & 255u], 1u);
        }
        __syncthreads();
        if (t < 32) {
            int r = rem_s;
            unsigned s = 0;
            #pragma unroll
            for (int k = 0; k < 8; k++) s += hist[255 - (lane * 8 + k)];
            unsigned pre = s;
            #pragma unroll
            for (int o = 1; o < 32; o <<= 1) { unsigned v = __shfl_up_sync(0xffffffffu, pre, o); if (lane >= o) pre += v; }
            bool hit = ((int)pre >= r) && (int)(pre - s) < r;
            unsigned mk = __ballot_sync(0xffffffffu, hit);
            if (lane == (__ffs(mk) - 1)) {
                unsigned cum = pre - s;
                for (int k = 0; k < 8; k++) {
                    int bin = 255 - (lane * 8 + k);
                    cum += hist[bin];
                    if ((int)cum >= r) { rem_s = r - (int)(cum - hist[bin]); pref_s = p | ((unsigned long long)bin << shift); break; }
                }
            }
        }
        __syncthreads();
    }
    unsigned long long kth = pref_s;
    for (int i = t; i < n; i += 1024) {
        if (cand[i] >= kth) {
            int pi = atomicAdd(&ocnt, 1);
            if (pi < 256) d_topk[b][ch - 1][pi] = (int)(0xFFFFFFFFu - (unsigned)(cand[i] & 0xFFFFFFFFull));
        }
    }
}

// ---------------- merge+sort 512 indices, gather embeddings ----------------
__global__ void __launch_bounds__(256) sortgather_kernel(const float* __restrict__ x_skip) {
    int b = blockIdx.x, t = threadIdx.x;
    __shared__ int s[512];
    s[t] = d_topk[b][0][t];
    s[256 + t] = d_topk[b][1][t];
    __syncthreads();
    for (int k = 2; k <= 512; k <<= 1) {
        for (int j = k >> 1; j > 0; j >>= 1) {
            #pragma unroll
            for (int half = 0; half < 2; half++) {
                int idx = half * 256 + t;
                int ixj = idx ^ j;
                if (ixj > idx) {
                    int a = s[idx], c = s[ixj];
                    bool up = ((idx & k) == 0);
                    if ((a > c) == up) { s[idx] = c; s[ixj] = a; }
                }
            }
            __syncthreads();
        }
    }
    d_idxg[b][t] = s[t];
    d_idxg[b][256 + t] = s[256 + t];
    __syncthreads();
    for (int q = t; q < 512 * 32; q += 256) {
        int i = q >> 5, c = q & 31;
        d_emb[(b * 512 + i) * 32 + c] = x_skip[((size_t)b * 32 + c) * LSEQ + s[i]];
    }
}

// ---------------- hybrid: blocks 0-2047 pos features; blocks 2048-2175 qkv layer 0 ----------------
__global__ void __launch_bounds__(256) posqkv_kernel(
    const float* __restrict__ ln1g, const float* __restrict__ ln1b,
    const float* __restrict__ Wq, const float* __restrict__ Wk, const float* __restrict__ Wv,
    const float* __restrict__ Wrel, const float* __restrict__ rcb, const float* __restrict__ rpb)
{
    __shared__ float h2s[256];
    __shared__ float qp[1024];
    __shared__ float Wrs[3870];
    int t = threadIdx.x, lane = t & 31, w = t >> 5;

    if (blockIdx.x < 2048) {
        // ---- positional basis features (layer-invariant, fp16 packed) ----
        unsigned int id = blockIdx.x * 256u + t;
        int b = id >> 18;
        unsigned int r = id & 262143u;
        int i = r >> 9, j = r & 511;
        int d = d_idxg[b][i] - d_idxg[b][j];
        float a = fabsf((float)d);
        float sg = (d > 0) ? 1.f : ((d < 0) ? -1.f : 0.f);
        float f[16];
        #pragma unroll
        for (int k = 0; k < 5; k++) f[k] = expf(d_cc[k] * a);
        f[5] = (1.f  > a) ? 1.f : 0.f;
        f[6] = (3.f  > a) ? 1.f : 0.f;
        f[7] = (7.f  > a) ? 1.f : 0.f;
        f[8] = (15.f > a) ? 1.f : 0.f;
        f[9] = (31.f > a) ? 1.f : 0.f;
        float la = logf(a);
        float invp = 1.0f / __int_as_float(d_pmaxbits);
        #pragma unroll
        for (int k = 0; k < 5; k++) {
            float lp = d_cc[15 + k] * la - d_cc[10 + k] * a;
            f[10 + k] = (expf(lp - d_cc[5 + k]) + 1e-8f) * invp;
        }
        f[15] = sg;
        unsigned u[8];
        #pragma unroll
        for (int k = 0; k < 8; k++) u[k] = h2u(__floats2half2_rn(f[2 * k], f[2 * k + 1]));
        uint4* o = d_posh4 + (size_t)id * 2u;
        o[0] = make_uint4(u[0], u[1], u[2], u[3]);
        o[1] = make_uint4(u[4], u[5], u[6], u[7]);
        return;
    }

    // ---- qkv for layer 0: 8 tokens/block, 256 threads ----
    int q = blockIdx.x - 2048;            // 0..127
    int b = q >> 6, i0 = (q & 63) * 8;

    for (int qq = t; qq < 3840; qq += 256) {
        int f = qq >> 7, c = qq & 127;
        Wrs[f * 129 + c] = Wrel[qq];      // lq = 0
    }
    // LN1 (warp per token, 8 warps)
    {
        float x = d_emb[(b * 512 + i0 + w) * 32 + lane];
        float s1 = x;
        #pragma unroll
        for (int o = 16; o > 0; o >>= 1) s1 += __shfl_xor_sync(0xffffffffu, s1, o);
        float mu = s1 * (1.f / 32.f);
        float dd = x - mu;
        float s2 = dd * dd;
        #pragma unroll
        for (int o = 16; o > 0; o >>= 1) s2 += __shfl_xor_sync(0xffffffffu, s2, o);
        float rs = rsqrtf(s2 * (1.f / 32.f) + 1e-5f);
        h2s[w * 32 + lane] = dd * rs * ln1g[lane] + ln1b[lane];
    }
    __syncthreads();
    // QKV: c = t&127, tg = t>>7 in {0,1}, 4 tokens each
    {
        int c = t & 127, tg = t >> 7;
        int hh = c >> 5, dd = c & 31;
        int bh = b * 4 + hh;
        float rc = rcb[hh * 32 + dd];
        float rp = rpb[hh * 32 + dd];
        float accq[4], acck[4], accv[4];
        #pragma unroll
        for (int tk = 0; tk < 4; tk++) { accq[tk] = 0.f; acck[tk] = 0.f; accv[tk] = 0.f; }
        #pragma unroll 8
        for (int cc = 0; cc < 32; cc++) {
            float a = Wq[cc * 128 + c], kwe = Wk[cc * 128 + c], vwe = Wv[cc * 128 + c];
            #pragma unroll
            for (int tk = 0; tk < 4; tk++) {
                float hc = h2s[(tg * 4 + tk) * 32 + cc];
                accq[tk] += hc * a; acck[tk] += hc * kwe; accv[tk] += hc * vwe;
            }
        }
        #pragma unroll
        for (int tk = 0; tk < 4; tk++) {
            int tok = tg * 4 + tk;
            float qv = accq[tk] * 0.17677669529663687f;
            d_qcb[(bh * 512 + i0 + tok) * 32 + dd] = qv + rc;
            qp[tok * 128 + c] = qv + rp;
        }
        uint2 kp, vp;
        kp.x = h2u(__floats2half2_rn(acck[0], acck[1]));
        kp.y = h2u(__floats2half2_rn(acck[2], acck[3]));
        vp.x = h2u(__floats2half2_rn(accv[0], accv[1]));
        vp.y = h2u(__floats2half2_rn(accv[2], accv[3]));
        *(uint2*)&d_kkh[(bh * 32 + dd) * 512 + i0 + tg * 4] = kp;
        *(uint2*)&d_vvh[(bh * 32 + dd) * 512 + i0 + tg * 4] = vp;
    }
    __syncthreads();
    // qrel: warp = token, lane = feature
    if (lane < 30) {
        int f = lane, tok = w;
        #pragma unroll
        for (int h2 = 0; h2 < 4; h2++) {
            float s = 0.f;
            #pragma unroll
            for (int d2 = 0; d2 < 32; d2++)
                s += Wrs[f * 129 + h2 * 32 + d2] * qp[tok * 128 + h2 * 32 + d2];
            d_qrl[((b * 512 + i0 + tok) * 4 + h2) * 32 + f] = s;
        }
    }
}

// ---------------- attention: 16 rows/block, 2 rows/warp, coalesced j-mapping ----------------
__global__ void __launch_bounds__(256, 2) attn_kernel() {
    extern __shared__ __align__(16) unsigned char smraw[];
    __half* Kh = (__half*)smraw;                       // 32KB [d][j]
    __half* Vh = (__half*)(smraw + 32768);             // 32KB
    float* qcs = (float*)(smraw + 65536);              // 512 f
    unsigned* qAh = (unsigned*)(smraw + 67584);        // 128 u
    unsigned* qBh = (unsigned*)(smraw + 68096);        // 128 u
    int t = threadIdx.x, lane = t & 31, w = t >> 5;
    int i0 = blockIdx.x * 16;
    int hd = blockIdx.y;
    int b = blockIdx.z;
    int bh = b * 4 + hd;

    {
        const uint4* kg = (const uint4*)(d_kkh + bh * 16384);
        const uint4* vg = (const uint4*)(d_vvh + bh * 16384);
        uint4* ks4 = (uint4*)Kh; uint4* vs4 = (uint4*)Vh;
        for (int q = t; q < 2048; q += 256) { ks4[q] = kg[q]; vs4[q] = vg[q]; }
    }
    for (int q = t; q < 512; q += 256)
        qcs[q] = d_qcb[(bh * 512 + i0 + (q >> 5)) * 32 + (q & 31)];
    if (t < 128) {
        int r = t >> 3, p = t & 7;
        const float* qr = d_qrl + (((b * 512) + i0 + r) * 4 + hd) * 32;
        int f0 = 2 * p, f1 = f0 + 1;
        float a0 = qr[f0],      a1 = (f1 < 15) ? qr[f1] : 0.f;
        float b0 = qr[15 + f0], b1 = (f1 < 15) ? qr[15 + f1] : 0.f;
        qAh[r * 8 + p] = h2u(__floats2half2_rn(a0, a1));
        qBh[r * 8 + p] = h2u(__floats2half2_rn(b0, b1));
    }
    __syncthreads();

    int r0 = 2 * w, r1 = r0 + 1;
    float s0[16], s1[16];
    #pragma unroll
    for (int q = 0; q < 16; q++) { s0[q] = 0.f; s1[q] = 0.f; }

    for (int d = 0; d < 32; d++) {
        float qv0 = qcs[r0 * 32 + d], qv1 = qcs[r1 * 32 + d];
        const __half* kr = Kh + d * 512;
        #pragma unroll
        for (int ch = 0; ch < 4; ch++) {
            #pragma unroll
            for (int u = 0; u < 4; u++) {
                float kv = __half2float(kr[ch * 128 + u * 32 + lane]);
                s0[ch * 4 + u] += qv0 * kv;
                s1[ch * 4 + u] += qv1 * kv;
            }
        }
    }

    {
        __half2 qa0[8], qb0[8], qa1[8], qb1[8];
        #pragma unroll
        for (int p = 0; p < 8; p++) {
            qa0[p] = u2h(qAh[r0 * 8 + p]); qb0[p] = u2h(qBh[r0 * 8 + p]);
            qa1[p] = u2h(qAh[r1 * 8 + p]); qb1[p] = u2h(qBh[r1 * 8 + p]);
        }
        const uint4* prow0 = d_posh4 + 2 * (size_t)((b * 512 + i0 + r0) * 512);
        const uint4* prow1 = d_posh4 + 2 * (size_t)((b * 512 + i0 + r1) * 512);
        #pragma unroll
        for (int ch = 0; ch < 4; ch++) {
            #pragma unroll
            for (int u = 0; u < 4; u++) {
                int j = ch * 128 + u * 32 + lane;
                {
                    uint4 A = prow0[2 * j], B = prow0[2 * j + 1];
                    __half2 sA = __hmul2(u2h(A.x), qa0[0]);
                    sA = __hfma2(u2h(A.y), qa0[1], sA); sA = __hfma2(u2h(A.z), qa0[2], sA);
                    sA = __hfma2(u2h(A.w), qa0[3], sA); sA = __hfma2(u2h(B.x), qa0[4], sA);
                    sA = __hfma2(u2h(B.y), qa0[5], sA); sA = __hfma2(u2h(B.z), qa0[6], sA);
                    sA = __hfma2(u2h(B.w), qa0[7], sA);
                    __half2 sB = __hmul2(u2h(A.x), qb0[0]);
                    sB = __hfma2(u2h(A.y), qb0[1], sB); sB = __hfma2(u2h(A.z), qb0[2], sB);
                    sB = __hfma2(u2h(A.w), qb0[3], sB); sB = __hfma2(u2h(B.x), qb0[4], sB);
                    sB = __hfma2(u2h(B.y), qb0[5], sB); sB = __hfma2(u2h(B.z), qb0[6], sB);
                    sB = __hfma2(u2h(B.w), qb0[7], sB);
                    float2 fA = __half22float2(sA), fB = __half22float2(sB);
                    float sg = __high2float(u2h(B.w));
                    s0[ch * 4 + u] += (fA.x + fA.y) + sg * (fB.x + fB.y);
                }
                {
                    uint4 A = prow1[2 * j], B = prow1[2 * j + 1];
                    __half2 sA = __hmul2(u2h(A.x), qa1[0]);
                    sA = __hfma2(u2h(A.y), qa1[1], sA); sA = __hfma2(u2h(A.z), qa1[2], sA);
                    sA = __hfma2(u2h(A.w), qa1[3], sA); sA = __hfma2(u2h(B.x), qa1[4], sA);
                    sA = __hfma2(u2h(B.y), qa1[5], sA); sA = __hfma2(u2h(B.z), qa1[6], sA);
                    sA = __hfma2(u2h(B.w), qa1[7], sA);
                    __half2 sB = __hmul2(u2h(A.x), qb1[0]);
                    sB = __hfma2(u2h(A.y), qb1[1], sB); sB = __hfma2(u2h(A.z), qb1[2], sB);
                    sB = __hfma2(u2h(A.w), qb1[3], sB); sB = __hfma2(u2h(B.x), qb1[4], sB);
                    sB = __hfma2(u2h(B.y), qb1[5], sB); sB = __hfma2(u2h(B.z), qb1[6], sB);
                    sB = __hfma2(u2h(B.w), qb1[7], sB);
                    float2 fA = __half22float2(sA), fB = __half22float2(sB);
                    float sg = __high2float(u2h(B.w));
                    s1[ch * 4 + u] += (fA.x + fA.y) + sg * (fB.x + fB.y);
                }
            }
        }
    }

    float m0 = -3.0e38f, m1 = -3.0e38f;
    #pragma unroll
    for (int q = 0; q < 16; q++) { m0 = fmaxf(m0, s0[q]); m1 = fmaxf(m1, s1[q]); }
    #pragma unroll
    for (int o = 16; o > 0; o >>= 1) {
        m0 = fmaxf(m0, __shfl_xor_sync(0xffffffffu, m0, o));
        m1 = fmaxf(m1, __shfl_xor_sync(0xffffffffu, m1, o));
    }
    float su0 = 0.f, su1 = 0.f;
    #pragma unroll
    for (int q = 0; q < 16; q++) {
        s0[q] = expf(s0[q] - m0); su0 += s0[q];
        s1[q] = expf(s1[q] - m1); su1 += s1[q];
    }
    #pragma unroll
    for (int o = 16; o > 0; o >>= 1) {
        su0 += __shfl_xor_sync(0xffffffffu, su0, o);
        su1 += __shfl_xor_sync(0xffffffffu, su1, o);
    }
    float inv0 = 1.f / su0, inv1 = 1.f / su1;

    #pragma unroll
    for (int pass = 0; pass < 2; pass++) {
        float v[32];
        #pragma unroll
        for (int k = 0; k < 16; k++) {
            int d = pass * 16 + k;
            const __half* vr = Vh + d * 512;
            float a0 = 0.f, a1 = 0.f;
            #pragma unroll
            for (int ch = 0; ch < 4; ch++) {
                #pragma unroll
                for (int u = 0; u < 4; u++) {
                    float vv = __half2float(vr[ch * 128 + u * 32 + lane]);
                    a0 += s0[ch * 4 + u] * vv;
                    a1 += s1[ch * 4 + u] * vv;
                }
            }
            v[k] = a0; v[16 + k] = a1;
        }
        #pragma unroll
        for (int m = 16; m >= 1; m >>= 1) {
            #pragma unroll
            for (int k = 0; k < m; k++) {
                float give = (lane & m) ? v[k] : v[k + m];
                float got = __shfl_xor_sync(0xffffffffu, give, m);
                v[k] = (lane & m) ? (v[k + m] + got) : (v[k] + got);
            }
        }
        float outv = v[0] * ((lane < 16) ? inv0 : inv1);
        int row = (lane < 16) ? r0 : r1;
        int dd = (lane & 15) + pass * 16;
        d_att[(b * 512 + i0 + row) * 128 + hd * 32 + dd] = outv;
    }
}

// ---------------- fused: [mlp lm] + [qkv lq], 8 tokens/block, 512 threads ----------------
__global__ void __launch_bounds__(512, 1) fused_kernel(
    const float* __restrict__ Wo, const float* __restrict__ bo,
    const float* __restrict__ ln2g, const float* __restrict__ ln2b,
    const float* __restrict__ W1, const float* __restrict__ b1,
    const float* __restrict__ W2, const float* __restrict__ b2,
    const float* __restrict__ ln1g, const float* __restrict__ ln1b,
    const float* __restrict__ Wq, const float* __restrict__ Wk, const float* __restrict__ Wv,
    const float* __restrict__ Wrel, const float* __restrict__ rcb, const float* __restrict__ rpb,
    float* __restrict__ out,
    int lm, int lq, int do_qkv)
{
    extern __shared__ float sm[];
    float* ats = sm;                  // 1024
    float* es  = sm + 1024;           // 256
    float* h2s = sm + 1280;           // 256
    float* tbs = sm + 1536;           // 4096
    float* red = sm + 5632;           // 4096
    float* qp  = sm + 9728;           // 1024
    float* Wrs = sm + 10752;          // 3870 -> 14622 floats total
    int t = threadIdx.x, lane = t & 31, w = t >> 5;
    int i0 = blockIdx.x * 8, b = blockIdx.y;

    if (do_qkv) {
        for (int q = t; q < 3840; q += 512) {
            int f = q >> 7, c = q & 127;
            Wrs[f * 129 + c] = Wrel[lq * 3840 + q];
        }
    }

    {
        for (int q = t; q < 1024; q += 512) ats[q] = d_att[(b * 512 + i0) * 128 + q];
        __syncthreads();
        {
            int oi = t >> 1, hf = t & 1;
            int tok = oi >> 5, c = oi & 31;
            const float* wo = Wo + lm * 4096;
            int mb = hf * 64;
            float acc = 0.f;
            #pragma unroll 16
            for (int m = 0; m < 64; m++) acc += ats[tok * 128 + mb + m] * wo[(mb + m) * 32 + c];
            acc += __shfl_xor_sync(0xffffffffu, acc, 1);
            if (hf == 0) es[oi] = d_emb[(b * 512 + i0 + tok) * 32 + c] + acc + bo[lm * 32 + c];
        }
        __syncthreads();
        if (w < 8) {
            float x = es[w * 32 + lane];
            float s1 = x;
            #pragma unroll
            for (int o = 16; o > 0; o >>= 1) s1 += __shfl_xor_sync(0xffffffffu, s1, o);
            float mu = s1 * (1.f / 32.f);
            float dd = x - mu;
            float s2 = dd * dd;
            #pragma unroll
            for (int o = 16; o > 0; o >>= 1) s2 += __shfl_xor_sync(0xffffffffu, s2, o);
            float rs = rsqrtf(s2 * (1.f / 32.f) + 1e-5f);
            h2s[w * 32 + lane] = dd * rs * ln2g[lm * 32 + lane] + ln2b[lm * 32 + lane];
        }
        __syncthreads();
        {
            int m = t;
            const float* w1 = W1 + lm * 16384;
            float wcol[32];
            #pragma unroll
            for (int cc = 0; cc < 32; cc++) wcol[cc] = w1[cc * 512 + m];
            float bb = b1[lm * 512 + m];
            #pragma unroll
            for (int tok = 0; tok < 8; tok++) {
                float s = bb;
                #pragma unroll
                for (int cc = 0; cc < 32; cc++) s += h2s[tok * 32 + cc] * wcol[cc];
                tbs[tok * 512 + m] = 0.5f * s * (1.f + erff(s * 0.70710678118654752f));
            }
        }
        __syncthreads();
        {
            const float* w2 = W2 + lm * 16384;
            int m0 = w * 32;
            float accw[8];
            #pragma unroll
            for (int tok = 0; tok < 8; tok++) accw[tok] = 0.f;
            #pragma unroll 4
            for (int mm = 0; mm < 32; mm++) {
                float w2v = w2[(m0 + mm) * 32 + lane];
                #pragma unroll
                for (int tok = 0; tok < 8; tok++) accw[tok] += tbs[tok * 512 + m0 + mm] * w2v;
            }
            #pragma unroll
            for (int tok = 0; tok < 8; tok++) red[(w * 8 + tok) * 32 + lane] = accw[tok];
        }
        __syncthreads();
        if (t < 256) {
            int tok = t >> 5, c = t & 31;
            float s = 0.f;
            #pragma unroll
            for (int ww = 0; ww < 16; ww++) s += red[(ww * 8 + tok) * 32 + c];
            float ne = es[t] + s + b2[lm * 32 + c];
            if (do_qkv) {
                d_emb[(b * 512 + i0 + tok) * 32 + c] = ne;
                es[t] = ne;
            } else {
                // last layer: scatter straight into output [B,C,L]
                out[((size_t)b * 32 + c) * LSEQ + d_idxg[b][i0 + tok]] = ne;
            }
        }
    }
    __syncthreads();

    if (!do_qkv) return;

    if (w < 8) {
        float x = es[w * 32 + lane];
        float s1 = x;
        #pragma unroll
        for (int o = 16; o > 0; o >>= 1) s1 += __shfl_xor_sync(0xffffffffu, s1, o);
        float mu = s1 * (1.f / 32.f);
        float dd = x - mu;
        float s2 = dd * dd;
        #pragma unroll
        for (int o = 16; o > 0; o >>= 1) s2 += __shfl_xor_sync(0xffffffffu, s2, o);
        float rs = rsqrtf(s2 * (1.f / 32.f) + 1e-5f);
        h2s[w * 32 + lane] = dd * rs * ln1g[lq * 32 + lane] + ln1b[lq * 32 + lane];
    }
    __syncthreads();
    {
        int c = t & 127, tg = t >> 7;
        int hh = c >> 5, dd = c & 31;
        int bh = b * 4 + hh;
        float rc = rcb[(lq * 4 + hh) * 32 + dd];
        float rp = rpb[(lq * 4 + hh) * 32 + dd];
        const float* wq = Wq + lq * 4096;
        const float* wk = Wk + lq * 4096;
        const float* wv = Wv + lq * 4096;
        float accq[2] = {0.f, 0.f}, acck[2] = {0.f, 0.f}, accv[2] = {0.f, 0.f};
        #pragma unroll 8
        for (int cc = 0; cc < 32; cc++) {
            float a = wq[cc * 128 + c], kwe = wk[cc * 128 + c], vwe = wv[cc * 128 + c];
            #pragma unroll
            for (int tk = 0; tk < 2; tk++) {
                float hc = h2s[(tg * 2 + tk) * 32 + cc];
                accq[tk] += hc * a; acck[tk] += hc * kwe; accv[tk] += hc * vwe;
            }
        }
        #pragma unroll
        for (int tk = 0; tk < 2; tk++) {
            int tok = tg * 2 + tk;
            float q = accq[tk] * 0.17677669529663687f;
            d_qcb[(bh * 512 + i0 + tok) * 32 + dd] = q + rc;
            qp[tok * 128 + c] = q + rp;
        }
        *(unsigned*)&d_kkh[(bh * 32 + dd) * 512 + i0 + tg * 2] = h2u(__floats2half2_rn(acck[0], acck[1]));
        *(unsigned*)&d_vvh[(bh * 32 + dd) * 512 + i0 + tg * 2] = h2u(__floats2half2_rn(accv[0], accv[1]));
    }
    __syncthreads();
    if (lane < 30) {
        int f = lane, tok = w >> 1, h2b = (w & 1) * 2;
        #pragma unroll
        for (int k = 0; k < 2; k++) {
            int hh2 = h2b + k;
            float s = 0.f;
            #pragma unroll
            for (int d2 = 0; d2 < 32; d2++)
                s += Wrs[f * 129 + hh2 * 32 + d2] * qp[tok * 128 + hh2 * 32 + d2];
            d_qrl[((b * 512 + i0 + tok) * 4 + hh2) * 32 + f] = s;
        }
    }
}

// ---------------- launch ----------------
extern "C" void kernel_launch(void* const* d_in, const int* in_sizes, int n_in,
                              void* d_out, int out_size) {
    (void)in_sizes; (void)n_in;
    const float* x_skip    = (const float*)d_in[0];
    const float* attention = (const float*)d_in[1];
    const float* ln1g = (const float*)d_in[2];
    const float* ln1b = (const float*)d_in[3];
    const float* Wq   = (const float*)d_in[4];
    const float* Wk   = (const float*)d_in[5];
    const float* Wv   = (const float*)d_in[6];
    const float* Wrel = (const float*)d_in[7];
    const float* rcb  = (const float*)d_in[8];
    const float* rpb  = (const float*)d_in[9];
    const float* Wo   = (const float*)d_in[10];
    const float* bo   = (const float*)d_in[11];
    const float* ln2g = (const float*)d_in[12];
    const float* ln2b = (const float*)d_in[13];
    const float* W1   = (const float*)d_in[14];
    const float* b1   = (const float*)d_in[15];
    const float* W2   = (const float*)d_in[16];
    const float* b2   = (const float*)d_in[17];
    float* out = (float*)d_out;

    const int ATT_SMEM   = 68608;
    const int FUSED_SMEM = 14622 * 4;             // 58488 B
    const int PRO_SMEM   = 32768 + 22528 + 1024;  // 56320 B
    cudaFuncSetAttribute(attn_kernel,     cudaFuncAttributeMaxDynamicSharedMemorySize, ATT_SMEM);
    cudaFuncSetAttribute(fused_kernel,    cudaFuncAttributeMaxDynamicSharedMemorySize, FUSED_SMEM);
    cudaFuncSetAttribute(prologue_kernel, cudaFuncAttributeMaxDynamicSharedMemorySize, PRO_SMEM);

    cudaMemsetAsync(d_out, 0, (size_t)out_size * sizeof(float), 0);
    prologue_kernel<<<36, 1024, PRO_SMEM>>>(attention);
    sortgather_kernel<<<2, 256>>>(x_skip);
    // pos features (2048 blocks) + layer-0 qkv (128 blocks) in ONE launch
    posqkv_kernel<<<2176, 256>>>(ln1g, ln1b, Wq, Wk, Wv, Wrel, rcb, rpb);

    for (int l = 0; l < 4; l++) {
        attn_kernel<<<dim3(32, 4, 2), 256, ATT_SMEM>>>();
        fused_kernel<<<dim3(64, 2), 512, FUSED_SMEM>>>(
            Wo, bo, ln2g, ln2b, W1, b1, W2, b2,
            ln1g, ln1b, Wq, Wk, Wv, Wrel, rcb, rpb, out,
            l, l + 1, /*do_qkv=*/(l < 3) ? 1 : 0);
    }
}

// round 15
// speedup vs baseline: 1.2971x; 1.0086x over previous
#include <cuda_runtime.h>
#include <cuda_fp16.h>
#include <math.h>

#define LSEQ 45000

// ---------------- device scratch (no allocs allowed) ----------------
__device__ uint4 d_posh4[1048576];          // [2][512][512] * 32B (16 halfs: 15 feats + sign)
__device__ int   d_topk[2][2][256];
__device__ int   d_idxg[2][512];
__device__ float d_emb[2*512*32];
__device__ __align__(16) __half d_kkh[2*4*32*512];   // [b*4+h][d][j] fp16
__device__ __align__(16) __half d_vvh[2*4*32*512];
__device__ float d_qcb[2*4*512*32];         // q*scale + rcb   [bh][i][d]
__device__ float d_qrl[2*512*4*32];         // layer-0 qrel only  [b][i][h][30 used]
__device__ __align__(16) __half d_relh[2*512*4*512]; // rel logits [b][i][h][j] fp16 (4MB)
__device__ float d_att[2*512*128];          // attention output pre-Wo
__device__ float d_cc[24];                  // 0..4 c1, 5..9 lz, 10..14 rate, 15..19 conc-1
__device__ int   d_pmaxbits;                // global gamma max (positive-float bits)

__device__ __forceinline__ __half2 u2h(unsigned u) { return *reinterpret_cast<__half2*>(&u); }
__device__ __forceinline__ unsigned h2u(__half2 h) { return *reinterpret_cast<unsigned*>(&h); }

// rel compute: warp = (row = w&7, jhalf = w>>3); qAh/qBh packed [ (r*4+h)*8 + p8 ]
__device__ __forceinline__ void compute_rel(const unsigned* qAh, const unsigned* qBh,
                                            int b, int i0, int t) {
    int lane = t & 31, w = t >> 5;
    int r = w & 7, jh = w >> 3;
    const uint4* prow = d_posh4 + 2 * (size_t)((b * 512 + i0 + r) * 512);
    unsigned* relbase = (unsigned*)d_relh;
    #pragma unroll
    for (int u2 = 0; u2 < 4; u2++) {
        int p = jh * 128 + u2 * 32 + lane;          // pair index, j = 2p, 2p+1
        uint4 A0 = prow[4 * p], B0 = prow[4 * p + 1];
        uint4 A1 = prow[4 * p + 2], B1 = prow[4 * p + 3];
        float sg0 = __high2float(u2h(B0.w));
        float sg1 = __high2float(u2h(B1.w));
        #pragma unroll
        for (int h = 0; h < 4; h++) {
            const unsigned* qa = qAh + (r * 4 + h) * 8;
            const unsigned* qb = qBh + (r * 4 + h) * 8;
            float v0, v1;
            {
                __half2 sA = __hmul2(u2h(A0.x), u2h(qa[0]));
                sA = __hfma2(u2h(A0.y), u2h(qa[1]), sA); sA = __hfma2(u2h(A0.z), u2h(qa[2]), sA);
                sA = __hfma2(u2h(A0.w), u2h(qa[3]), sA); sA = __hfma2(u2h(B0.x), u2h(qa[4]), sA);
                sA = __hfma2(u2h(B0.y), u2h(qa[5]), sA); sA = __hfma2(u2h(B0.z), u2h(qa[6]), sA);
                sA = __hfma2(u2h(B0.w), u2h(qa[7]), sA);
                __half2 sB = __hmul2(u2h(A0.x), u2h(qb[0]));
                sB = __hfma2(u2h(A0.y), u2h(qb[1]), sB); sB = __hfma2(u2h(A0.z), u2h(qb[2]), sB);
                sB = __hfma2(u2h(A0.w), u2h(qb[3]), sB); sB = __hfma2(u2h(B0.x), u2h(qb[4]), sB);
                sB = __hfma2(u2h(B0.y), u2h(qb[5]), sB); sB = __hfma2(u2h(B0.z), u2h(qb[6]), sB);
                sB = __hfma2(u2h(B0.w), u2h(qb[7]), sB);
                float2 fA = __half22float2(sA), fB = __half22float2(sB);
                v0 = (fA.x + fA.y) + sg0 * (fB.x + fB.y);
            }
            {
                __half2 sA = __hmul2(u2h(A1.x), u2h(qa[0]));
                sA = __hfma2(u2h(A1.y), u2h(qa[1]), sA); sA = __hfma2(u2h(A1.z), u2h(qa[2]), sA);
                sA = __hfma2(u2h(A1.w), u2h(qa[3]), sA); sA = __hfma2(u2h(B1.x), u2h(qa[4]), sA);
                sA = __hfma2(u2h(B1.y), u2h(qa[5]), sA); sA = __hfma2(u2h(B1.z), u2h(qa[6]), sA);
                sA = __hfma2(u2h(B1.w), u2h(qa[7]), sA);
                __half2 sB = __hmul2(u2h(A1.x), u2h(qb[0]));
                sB = __hfma2(u2h(A1.y), u2h(qb[1]), sB); sB = __hfma2(u2h(A1.z), u2h(qb[2]), sB);
                sB = __hfma2(u2h(A1.w), u2h(qb[3]), sB); sB = __hfma2(u2h(B1.x), u2h(qb[4]), sB);
                sB = __hfma2(u2h(B1.y), u2h(qb[5]), sB); sB = __hfma2(u2h(B1.z), u2h(qb[6]), sB);
                sB = __hfma2(u2h(B1.w), u2h(qb[7]), sB);
                float2 fA = __half22float2(sA), fB = __half22float2(sB);
                v1 = (fA.x + fA.y) + sg1 * (fB.x + fB.y);
            }
            relbase[((size_t)((b * 512 + i0 + r) * 4 + h)) * 256 + p] = h2u(__floats2half2_rn(v0, v1));
        }
    }
}

// ---------------- prologue: blocks 0-3 top-256 select, blocks 4-35 basis setup ----------------
#define TK_CAP 2816
__global__ void __launch_bounds__(1024) prologue_kernel(const float* __restrict__ att) {
    extern __shared__ unsigned char tks[];
    int t = threadIdx.x, lane = t & 31;

    if (blockIdx.x >= 4) {
        float* red = (float*)tks;
        int bid = blockIdx.x - 4;
        double L2S = log(45000.0) / log(2.0);
        float c1[5], lz[5], rate[5], cm1[5];
        for (int k = 0; k < 5; k++) {
            double lin = 3.0 + (L2S - 3.0) * ((double)k / 4.0);
            float hl = (float)exp2(lin);
            c1[k] = -0.69314718055994531f / hl;
            double mean = 9000.0 * (k + 1);
            double sd = 4500.0;
            float conc = (float)((mean / sd) * (mean / sd));
            float rt = (float)(mean / (sd * sd));
            rate[k] = rt; cm1[k] = conc - 1.0f;
            lz[k] = lgammaf(conc) - conc * logf(rt);
        }
        float m = 1e-8f;
        for (int a_ = bid * 1024 + t; a_ < LSEQ; a_ += 32768) {
            if (a_ == 0) continue;
            float a = (float)a_;
            float la = logf(a);
            for (int k = 0; k < 5; k++) {
                float p = expf(cm1[k] * la - rate[k] * a - lz[k]) + 1e-8f;
                m = fmaxf(m, p);
            }
        }
        red[t] = m; __syncthreads();
        for (int s = 512; s > 0; s >>= 1) {
            if (t < s) red[t] = fmaxf(red[t], red[t + s]);
            __syncthreads();
        }
        if (t == 0) atomicMax(&d_pmaxbits, __float_as_int(red[0]));
        if (bid == 0 && t == 0) {
            for (int k = 0; k < 5; k++) { d_cc[k] = c1[k]; d_cc[5+k] = lz[k]; d_cc[10+k] = rate[k]; d_cc[15+k] = cm1[k]; }
        }
        return;
    }

    unsigned* hist = (unsigned*)tks;
    unsigned long long* cand = (unsigned long long*)(tks + 32768);
    unsigned* ps = (unsigned*)(tks + 32768 + 22528);
    __shared__ unsigned thrT;
    __shared__ int cnt, ocnt, rem_s;
    __shared__ unsigned long long pref_s;
    int b = blockIdx.x >> 1, ch = (blockIdx.x & 1) + 1;
    const float* vals = att + (size_t)(b * 3 + ch) * LSEQ;
    for (int i = t; i < 8192; i += 1024) hist[i] = 0;
    if (t == 0) { cnt = 0; ocnt = 0; pref_s = 0ull; rem_s = 256; }
    __syncthreads();
    for (int j = t; j < LSEQ; j += 1024) {
        unsigned u = __float_as_uint(vals[j]);
        u = (u & 0x80000000u) ? ~u : (u | 0x80000000u);
        atomicAdd(&hist[u >> 19], 1u);
    }
    __syncthreads();
    if (t < 256) {
        unsigned sum = 0;
        int base = 8191 - t * 32;
        for (int k = 0; k < 32; k++) sum += hist[base - k];
        ps[t] = sum;
    }
    __syncthreads();
    if (t < 32) {
        unsigned s = 0;
        #pragma unroll
        for (int k = 0; k < 8; k++) s += ps[lane * 8 + k];
        unsigned pre = s;
        #pragma unroll
        for (int o = 1; o < 32; o <<= 1) { unsigned v = __shfl_up_sync(0xffffffffu, pre, o); if (lane >= o) pre += v; }
        bool hit = (pre >= 256u) && (pre - s) < 256u;
        unsigned mk = __ballot_sync(0xffffffffu, hit);
        if (lane == (__ffs(mk) - 1)) {
            unsigned cum = pre - s;
            int T = 0;
            for (int k = 0; k < 8; k++) {
                int ci = lane * 8 + k;
                if (cum + ps[ci] >= 256u) {
                    int base = 8191 - ci * 32;
                    for (int kk = 0; kk < 32; kk++) { cum += hist[base - kk]; if (cum >= 256u) { T = base - kk; break; } }
                    break;
                }
                cum += ps[ci];
            }
            thrT = (unsigned)T;
        }
    }
    __syncthreads();
    unsigned T = thrT;
    for (int j = t; j < LSEQ; j += 1024) {
        unsigned u = __float_as_uint(vals[j]);
        u = (u & 0x80000000u) ? ~u : (u | 0x80000000u);
        if ((u >> 19) >= T) {
            int pi = atomicAdd(&cnt, 1);
            if (pi < TK_CAP) cand[pi] = (((unsigned long long)u) << 32) | (unsigned)(0xFFFFFFFFu - (unsigned)j);
        }
    }
    __syncthreads();
    int n = cnt < TK_CAP ? cnt : TK_CAP;
    for (int shift = 56; shift >= 0; shift -= 8) {
        if (t < 256) hist[t] = 0;
        __syncthreads();
        unsigned long long p = pref_s;
        unsigned long long mh = (shift == 56) ? 0ull : ~((1ull << (shift + 8)) - 1ull);
        for (int i = t; i < n; i += 1024) {
            unsigned long long k = cand[i];
            if ((k & mh) == p) atomicAdd(&hist[(unsigned)(k >> shift) & 255u], 1u);
        }
        __syncthreads();
        if (t < 32) {
            int r = rem_s;
            unsigned s = 0;
            #pragma unroll
            for (int k = 0; k < 8; k++) s += hist[255 - (lane * 8 + k)];
            unsigned pre = s;
            #pragma unroll
            for (int o = 1; o < 32; o <<= 1) { unsigned v = __shfl_up_sync(0xffffffffu, pre, o); if (lane >= o) pre += v; }
            bool hit = ((int)pre >= r) && (int)(pre - s) < r;
            unsigned mk = __ballot_sync(0xffffffffu, hit);
            if (lane == (__ffs(mk) - 1)) {
                unsigned cum = pre - s;
                for (int k = 0; k < 8; k++) {
                    int bin = 255 - (lane * 8 + k);
                    cum += hist[bin];
                    if ((int)cum >= r) { rem_s = r - (int)(cum - hist[bin]); pref_s = p | ((unsigned long long)bin << shift); break; }
                }
            }
        }
        __syncthreads();
    }
    unsigned long long kth = pref_s;
    for (int i = t; i < n; i += 1024) {
        if (cand[i] >= kth) {
            int pi = atomicAdd(&ocnt, 1);
            if (pi < 256) d_topk[b][ch - 1][pi] = (int)(0xFFFFFFFFu - (unsigned)(cand[i] & 0xFFFFFFFFull));
        }
    }
}

// ---------------- merge+sort 512 indices, gather embeddings ----------------
__global__ void __launch_bounds__(256) sortgather_kernel(const float* __restrict__ x_skip) {
    int b = blockIdx.x, t = threadIdx.x;
    __shared__ int s[512];
    s[t] = d_topk[b][0][t];
    s[256 + t] = d_topk[b][1][t];
    __syncthreads();
    for (int k = 2; k <= 512; k <<= 1) {
        for (int j = k >> 1; j > 0; j >>= 1) {
            #pragma unroll
            for (int half = 0; half < 2; half++) {
                int idx = half * 256 + t;
                int ixj = idx ^ j;
                if (ixj > idx) {
                    int a = s[idx], c = s[ixj];
                    bool up = ((idx & k) == 0);
                    if ((a > c) == up) { s[idx] = c; s[ixj] = a; }
                }
            }
            __syncthreads();
        }
    }
    d_idxg[b][t] = s[t];
    d_idxg[b][256 + t] = s[256 + t];
    __syncthreads();
    for (int q = t; q < 512 * 32; q += 256) {
        int i = q >> 5, c = q & 31;
        d_emb[(b * 512 + i) * 32 + c] = x_skip[((size_t)b * 32 + c) * LSEQ + s[i]];
    }
}

// ---------------- hybrid: blocks 0-2047 pos features; blocks 2048-2175 qkv layer 0 ----------------
__global__ void __launch_bounds__(256) posqkv_kernel(
    const float* __restrict__ ln1g, const float* __restrict__ ln1b,
    const float* __restrict__ Wq, const float* __restrict__ Wk, const float* __restrict__ Wv,
    const float* __restrict__ Wrel, const float* __restrict__ rcb, const float* __restrict__ rpb)
{
    __shared__ float h2s[256];
    __shared__ float qp[1024];
    __shared__ float Wrs[3870];
    int t = threadIdx.x, lane = t & 31, w = t >> 5;

    if (blockIdx.x < 2048) {
        unsigned int id = blockIdx.x * 256u + t;
        int b = id >> 18;
        unsigned int r = id & 262143u;
        int i = r >> 9, j = r & 511;
        int d = d_idxg[b][i] - d_idxg[b][j];
        float a = fabsf((float)d);
        float sg = (d > 0) ? 1.f : ((d < 0) ? -1.f : 0.f);
        float f[16];
        #pragma unroll
        for (int k = 0; k < 5; k++) f[k] = expf(d_cc[k] * a);
        f[5] = (1.f  > a) ? 1.f : 0.f;
        f[6] = (3.f  > a) ? 1.f : 0.f;
        f[7] = (7.f  > a) ? 1.f : 0.f;
        f[8] = (15.f > a) ? 1.f : 0.f;
        f[9] = (31.f > a) ? 1.f : 0.f;
        float la = logf(a);
        float invp = 1.0f / __int_as_float(d_pmaxbits);
        #pragma unroll
        for (int k = 0; k < 5; k++) {
            float lp = d_cc[15 + k] * la - d_cc[10 + k] * a;
            f[10 + k] = (expf(lp - d_cc[5 + k]) + 1e-8f) * invp;
        }
        f[15] = sg;
        unsigned u[8];
        #pragma unroll
        for (int k = 0; k < 8; k++) u[k] = h2u(__floats2half2_rn(f[2 * k], f[2 * k + 1]));
        uint4* o = d_posh4 + (size_t)id * 2u;
        o[0] = make_uint4(u[0], u[1], u[2], u[3]);
        o[1] = make_uint4(u[4], u[5], u[6], u[7]);
        return;
    }

    int q = blockIdx.x - 2048;            // 0..127
    int b = q >> 6, i0 = (q & 63) * 8;

    for (int qq = t; qq < 3840; qq += 256) {
        int f = qq >> 7, c = qq & 127;
        Wrs[f * 129 + c] = Wrel[qq];      // lq = 0
    }
    {
        float x = d_emb[(b * 512 + i0 + w) * 32 + lane];
        float s1 = x;
        #pragma unroll
        for (int o = 16; o > 0; o >>= 1) s1 += __shfl_xor_sync(0xffffffffu, s1, o);
        float mu = s1 * (1.f / 32.f);
        float dd = x - mu;
        float s2 = dd * dd;
        #pragma unroll
        for (int o = 16; o > 0; o >>= 1) s2 += __shfl_xor_sync(0xffffffffu, s2, o);
        float rs = rsqrtf(s2 * (1.f / 32.f) + 1e-5f);
        h2s[w * 32 + lane] = dd * rs * ln1g[lane] + ln1b[lane];
    }
    __syncthreads();
    {
        int c = t & 127, tg = t >> 7;
        int hh = c >> 5, dd = c & 31;
        int bh = b * 4 + hh;
        float rc = rcb[hh * 32 + dd];
        float rp = rpb[hh * 32 + dd];
        float accq[4], acck[4], accv[4];
        #pragma unroll
        for (int tk = 0; tk < 4; tk++) { accq[tk] = 0.f; acck[tk] = 0.f; accv[tk] = 0.f; }
        #pragma unroll 8
        for (int cc = 0; cc < 32; cc++) {
            float a = Wq[cc * 128 + c], kwe = Wk[cc * 128 + c], vwe = Wv[cc * 128 + c];
            #pragma unroll
            for (int tk = 0; tk < 4; tk++) {
                float hc = h2s[(tg * 4 + tk) * 32 + cc];
                accq[tk] += hc * a; acck[tk] += hc * kwe; accv[tk] += hc * vwe;
            }
        }
        #pragma unroll
        for (int tk = 0; tk < 4; tk++) {
            int tok = tg * 4 + tk;
            float qv = accq[tk] * 0.17677669529663687f;
            d_qcb[(bh * 512 + i0 + tok) * 32 + dd] = qv + rc;
            qp[tok * 128 + c] = qv + rp;
        }
        uint2 kp, vp;
        kp.x = h2u(__floats2half2_rn(acck[0], acck[1]));
        kp.y = h2u(__floats2half2_rn(acck[2], acck[3]));
        vp.x = h2u(__floats2half2_rn(accv[0], accv[1]));
        vp.y = h2u(__floats2half2_rn(accv[2], accv[3]));
        *(uint2*)&d_kkh[(bh * 32 + dd) * 512 + i0 + tg * 4] = kp;
        *(uint2*)&d_vvh[(bh * 32 + dd) * 512 + i0 + tg * 4] = vp;
    }
    __syncthreads();
    if (lane < 30) {
        int f = lane, tok = w;
        #pragma unroll
        for (int h2 = 0; h2 < 4; h2++) {
            float s = 0.f;
            #pragma unroll
            for (int d2 = 0; d2 < 32; d2++)
                s += Wrs[f * 129 + h2 * 32 + d2] * qp[tok * 128 + h2 * 32 + d2];
            d_qrl[((b * 512 + i0 + tok) * 4 + h2) * 32 + f] = s;
        }
    }
}

// ---------------- rel for layer 0 (reads d_qrl written by posqkv) ----------------
__global__ void __launch_bounds__(512) rel0_kernel() {
    __shared__ unsigned qAh[256], qBh[256];
    int t = threadIdx.x;
    int i0 = blockIdx.x * 8, b = blockIdx.y;
    if (t < 256) {
        int unit = t >> 3, p8 = t & 7;
        int r = unit >> 2, h = unit & 3;
        const float* qr = d_qrl + ((b * 512 + i0 + r) * 4 + h) * 32;
        int f0 = 2 * p8, f1 = f0 + 1;
        float a0 = qr[f0],      a1 = (f1 < 15) ? qr[f1] : 0.f;
        float b0 = qr[15 + f0], b1 = (f1 < 15) ? qr[15 + f1] : 0.f;
        qAh[unit * 8 + p8] = h2u(__floats2half2_rn(a0, a1));
        qBh[unit * 8 + p8] = h2u(__floats2half2_rn(b0, b1));
    }
    __syncthreads();
    compute_rel(qAh, qBh, b, i0, t);
}

// ---------------- attention: 16 rows/block, 2 rows/warp, half2 loads, rel from d_relh ----------------
__global__ void __launch_bounds__(256, 2) attn_kernel() {
    extern __shared__ __align__(16) unsigned char smraw[];
    __half* Kh = (__half*)smraw;                       // 32KB [d][j]
    __half* Vh = (__half*)(smraw + 32768);             // 32KB
    float* qcs = (float*)(smraw + 65536);              // 512 f
    int t = threadIdx.x, lane = t & 31, w = t >> 5;
    int i0 = blockIdx.x * 16;
    int hd = blockIdx.y;
    int b = blockIdx.z;
    int bh = b * 4 + hd;

    {
        const uint4* kg = (const uint4*)(d_kkh + bh * 16384);
        const uint4* vg = (const uint4*)(d_vvh + bh * 16384);
        uint4* ks4 = (uint4*)Kh; uint4* vs4 = (uint4*)Vh;
        for (int q = t; q < 2048; q += 256) { ks4[q] = kg[q]; vs4[q] = vg[q]; }
    }
    for (int q = t; q < 512; q += 256)
        qcs[q] = d_qcb[(bh * 512 + i0 + (q >> 5)) * 32 + (q & 31)];
    __syncthreads();

    int r0 = 2 * w, r1 = r0 + 1;
    // pair mapping: p = ch*64 + u2*32 + lane; j = 2p, 2p+1; s idx = (ch*2+u2)*2 + e
    float s0[16], s1[16];
    #pragma unroll
    for (int q = 0; q < 16; q++) { s0[q] = 0.f; s1[q] = 0.f; }

    for (int d = 0; d < 32; d++) {
        float qv0 = qcs[r0 * 32 + d], qv1 = qcs[r1 * 32 + d];
        const unsigned* kr = (const unsigned*)(Kh + d * 512);
        #pragma unroll
        for (int ch = 0; ch < 4; ch++) {
            #pragma unroll
            for (int u2 = 0; u2 < 2; u2++) {
                float2 f = __half22float2(u2h(kr[ch * 64 + u2 * 32 + lane]));
                int idx = (ch * 2 + u2) * 2;
                s0[idx] += qv0 * f.x; s0[idx + 1] += qv0 * f.y;
                s1[idx] += qv1 * f.x; s1[idx + 1] += qv1 * f.y;
            }
        }
    }
    // rel add (coalesced fp16 rows)
    {
        const unsigned* rr0 = (const unsigned*)d_relh + ((size_t)((b * 512 + i0 + r0) * 4 + hd)) * 256;
        const unsigned* rr1 = (const unsigned*)d_relh + ((size_t)((b * 512 + i0 + r1) * 4 + hd)) * 256;
        #pragma unroll
        for (int ch = 0; ch < 4; ch++) {
            #pragma unroll
            for (int u2 = 0; u2 < 2; u2++) {
                int p = ch * 64 + u2 * 32 + lane;
                int idx = (ch * 2 + u2) * 2;
                float2 f0 = __half22float2(u2h(rr0[p]));
                float2 f1 = __half22float2(u2h(rr1[p]));
                s0[idx] += f0.x; s0[idx + 1] += f0.y;
                s1[idx] += f1.x; s1[idx + 1] += f1.y;
            }
        }
    }

    float m0 = -3.0e38f, m1 = -3.0e38f;
    #pragma unroll
    for (int q = 0; q < 16; q++) { m0 = fmaxf(m0, s0[q]); m1 = fmaxf(m1, s1[q]); }
    #pragma unroll
    for (int o = 16; o > 0; o >>= 1) {
        m0 = fmaxf(m0, __shfl_xor_sync(0xffffffffu, m0, o));
        m1 = fmaxf(m1, __shfl_xor_sync(0xffffffffu, m1, o));
    }
    float su0 = 0.f, su1 = 0.f;
    #pragma unroll
    for (int q = 0; q < 16; q++) {
        s0[q] = expf(s0[q] - m0); su0 += s0[q];
        s1[q] = expf(s1[q] - m1); su1 += s1[q];
    }
    #pragma unroll
    for (int o = 16; o > 0; o >>= 1) {
        su0 += __shfl_xor_sync(0xffffffffu, su0, o);
        su1 += __shfl_xor_sync(0xffffffffu, su1, o);
    }
    float inv0 = 1.f / su0, inv1 = 1.f / su1;

    #pragma unroll
    for (int pass = 0; pass < 2; pass++) {
        float v[32];
        #pragma unroll
        for (int k = 0; k < 16; k++) {
            int d = pass * 16 + k;
            const unsigned* vr = (const unsigned*)(Vh + d * 512);
            float a0 = 0.f, a1 = 0.f;
            #pragma unroll
            for (int ch = 0; ch < 4; ch++) {
                #pragma unroll
                for (int u2 = 0; u2 < 2; u2++) {
                    float2 f = __half22float2(u2h(vr[ch * 64 + u2 * 32 + lane]));
                    int idx = (ch * 2 + u2) * 2;
                    a0 += s0[idx] * f.x + s0[idx + 1] * f.y;
                    a1 += s1[idx] * f.x + s1[idx + 1] * f.y;
                }
            }
            v[k] = a0; v[16 + k] = a1;
        }
        #pragma unroll
        for (int m = 16; m >= 1; m >>= 1) {
            #pragma unroll
            for (int k = 0; k < m; k++) {
                float give = (lane & m) ? v[k] : v[k + m];
                float got = __shfl_xor_sync(0xffffffffu, give, m);
                v[k] = (lane & m) ? (v[k + m] + got) : (v[k] + got);
            }
        }
        float outv = v[0] * ((lane < 16) ? inv0 : inv1);
        int row = (lane < 16) ? r0 : r1;
        int dd = (lane & 15) + pass * 16;
        d_att[(b * 512 + i0 + row) * 128 + hd * 32 + dd] = outv;
    }
}

// ---------------- fused: mlp(lm) + qkv(lq) + rel(lq), 8 tokens/block, 512 threads ----------------
__global__ void __launch_bounds__(512, 1) fused_kernel(
    const float* __restrict__ Wo, const float* __restrict__ bo,
    const float* __restrict__ ln2g, const float* __restrict__ ln2b,
    const float* __restrict__ W1, const float* __restrict__ b1,
    const float* __restrict__ W2, const float* __restrict__ b2,
    const float* __restrict__ ln1g, const float* __restrict__ ln1b,
    const float* __restrict__ Wq, const float* __restrict__ Wk, const float* __restrict__ Wv,
    const float* __restrict__ Wrel, const float* __restrict__ rcb, const float* __restrict__ rpb,
    float* __restrict__ out,
    int lm, int lq, int do_qkv)
{
    extern __shared__ float sm[];
    float* ats = sm;                  // 1024
    float* es  = sm + 1024;           // 256
    float* h2s = sm + 1280;           // 256
    float* tbs = sm + 1536;           // 4096 (reused: qrs floats)
    float* red = sm + 5632;           // 4096 (reused: qAh/qBh)
    float* qp  = sm + 9728;           // 1024
    float* Wrs = sm + 10752;          // 3870 -> 14622 floats total
    int t = threadIdx.x, lane = t & 31, w = t >> 5;
    int i0 = blockIdx.x * 8, b = blockIdx.y;

    if (do_qkv) {
        for (int q = t; q < 3840; q += 512) {
            int f = q >> 7, c = q & 127;
            Wrs[f * 129 + c] = Wrel[lq * 3840 + q];
        }
    }

    {
        for (int q = t; q < 1024; q += 512) ats[q] = d_att[(b * 512 + i0) * 128 + q];
        __syncthreads();
        {
            int oi = t >> 1, hf = t & 1;
            int tok = oi >> 5, c = oi & 31;
            const float* wo = Wo + lm * 4096;
            int mb = hf * 64;
            float acc = 0.f;
            #pragma unroll 16
            for (int m = 0; m < 64; m++) acc += ats[tok * 128 + mb + m] * wo[(mb + m) * 32 + c];
            acc += __shfl_xor_sync(0xffffffffu, acc, 1);
            if (hf == 0) es[oi] = d_emb[(b * 512 + i0 + tok) * 32 + c] + acc + bo[lm * 32 + c];
        }
        __syncthreads();
        if (w < 8) {
            float x = es[w * 32 + lane];
            float s1 = x;
            #pragma unroll
            for (int o = 16; o > 0; o >>= 1) s1 += __shfl_xor_sync(0xffffffffu, s1, o);
            float mu = s1 * (1.f / 32.f);
            float dd = x - mu;
            float s2 = dd * dd;
            #pragma unroll
            for (int o = 16; o > 0; o >>= 1) s2 += __shfl_xor_sync(0xffffffffu, s2, o);
            float rs = rsqrtf(s2 * (1.f / 32.f) + 1e-5f);
            h2s[w * 32 + lane] = dd * rs * ln2g[lm * 32 + lane] + ln2b[lm * 32 + lane];
        }
        __syncthreads();
        {
            int m = t;
            const float* w1 = W1 + lm * 16384;
            float wcol[32];
            #pragma unroll
            for (int cc = 0; cc < 32; cc++) wcol[cc] = w1[cc * 512 + m];
            float bb = b1[lm * 512 + m];
            #pragma unroll
            for (int tok = 0; tok < 8; tok++) {
                float s = bb;
                #pragma unroll
                for (int cc = 0; cc < 32; cc++) s += h2s[tok * 32 + cc] * wcol[cc];
                tbs[tok * 512 + m] = 0.5f * s * (1.f + erff(s * 0.70710678118654752f));
            }
        }
        __syncthreads();
        {
            const float* w2 = W2 + lm * 16384;
            int m0 = w * 32;
            float accw[8];
            #pragma unroll
            for (int tok = 0; tok < 8; tok++) accw[tok] = 0.f;
            #pragma unroll 4
            for (int mm = 0; mm < 32; mm++) {
                float w2v = w2[(m0 + mm) * 32 + lane];
                #pragma unroll
                for (int tok = 0; tok < 8; tok++) accw[tok] += tbs[tok * 512 + m0 + mm] * w2v;
            }
            #pragma unroll
            for (int tok = 0; tok < 8; tok++) red[(w * 8 + tok) * 32 + lane] = accw[tok];
        }
        __syncthreads();
        if (t < 256) {
            int tok = t >> 5, c = t & 31;
            float s = 0.f;
            #pragma unroll
            for (int ww = 0; ww < 16; ww++) s += red[(ww * 8 + tok) * 32 + c];
            float ne = es[t] + s + b2[lm * 32 + c];
            if (do_qkv) {
                d_emb[(b * 512 + i0 + tok) * 32 + c] = ne;
                es[t] = ne;
            } else {
                out[((size_t)b * 32 + c) * LSEQ + d_idxg[b][i0 + tok]] = ne;
            }
        }
    }
    __syncthreads();

    if (!do_qkv) return;

    if (w < 8) {
        float x = es[w * 32 + lane];
        float s1 = x;
        #pragma unroll
        for (int o = 16; o > 0; o >>= 1) s1 += __shfl_xor_sync(0xffffffffu, s1, o);
        float mu = s1 * (1.f / 32.f);
        float dd = x - mu;
        float s2 = dd * dd;
        #pragma unroll
        for (int o = 16; o > 0; o >>= 1) s2 += __shfl_xor_sync(0xffffffffu, s2, o);
        float rs = rsqrtf(s2 * (1.f / 32.f) + 1e-5f);
        h2s[w * 32 + lane] = dd * rs * ln1g[lq * 32 + lane] + ln1b[lq * 32 + lane];
    }
    __syncthreads();
    {
        int c = t & 127, tg = t >> 7;
        int hh = c >> 5, dd = c & 31;
        int bh = b * 4 + hh;
        float rc = rcb[(lq * 4 + hh) * 32 + dd];
        float rp = rpb[(lq * 4 + hh) * 32 + dd];
        const float* wq = Wq + lq * 4096;
        const float* wk = Wk + lq * 4096;
        const float* wv = Wv + lq * 4096;
        float accq[2] = {0.f, 0.f}, acck[2] = {0.f, 0.f}, accv[2] = {0.f, 0.f};
        #pragma unroll 8
        for (int cc = 0; cc < 32; cc++) {
            float a = wq[cc * 128 + c], kwe = wk[cc * 128 + c], vwe = wv[cc * 128 + c];
            #pragma unroll
            for (int tk = 0; tk < 2; tk++) {
                float hc = h2s[(tg * 2 + tk) * 32 + cc];
                accq[tk] += hc * a; acck[tk] += hc * kwe; accv[tk] += hc * vwe;
            }
        }
        #pragma unroll
        for (int tk = 0; tk < 2; tk++) {
            int tok = tg * 2 + tk;
            float q = accq[tk] * 0.17677669529663687f;
            d_qcb[(bh * 512 + i0 + tok) * 32 + dd] = q + rc;
            qp[tok * 128 + c] = q + rp;
        }
        *(unsigned*)&d_kkh[(bh * 32 + dd) * 512 + i0 + tg * 2] = h2u(__floats2half2_rn(acck[0], acck[1]));
        *(unsigned*)&d_vvh[(bh * 32 + dd) * 512 + i0 + tg * 2] = h2u(__floats2half2_rn(accv[0], accv[1]));
    }
    __syncthreads();
    // qrel into smem qrs (tbs reuse)
    float* qrs = tbs;     // [ (tok*4+h)*32 + f ]
    if (lane < 30) {
        int f = lane, tok = w >> 1, h2b = (w & 1) * 2;
        #pragma unroll
        for (int k = 0; k < 2; k++) {
            int hh2 = h2b + k;
            float s = 0.f;
            #pragma unroll
            for (int d2 = 0; d2 < 32; d2++)
                s += Wrs[f * 129 + hh2 * 32 + d2] * qp[tok * 128 + hh2 * 32 + d2];
            qrs[(tok * 4 + hh2) * 32 + f] = s;
        }
    }
    __syncthreads();
    // pack half2 q-vectors
    unsigned* qAh = (unsigned*)red;
    unsigned* qBh = qAh + 256;
    if (t < 256) {
        int unit = t >> 3, p8 = t & 7;
        int f0 = 2 * p8, f1 = f0 + 1;
        float a0 = qrs[unit * 32 + f0],      a1 = (f1 < 15) ? qrs[unit * 32 + f1] : 0.f;
        float b0 = qrs[unit * 32 + 15 + f0], b1 = (f1 < 15) ? qrs[unit * 32 + 15 + f1] : 0.f;
        qAh[unit * 8 + p8] = h2u(__floats2half2_rn(a0, a1));
        qBh[unit * 8 + p8] = h2u(__floats2half2_rn(b0, b1));
    }
    __syncthreads();
    compute_rel(qAh, qBh, b, i0, t);
}

// ---------------- launch ----------------
extern "C" void kernel_launch(void* const* d_in, const int* in_sizes, int n_in,
                              void* d_out, int out_size) {
    (void)in_sizes; (void)n_in;
    const float* x_skip    = (const float*)d_in[0];
    const float* attention = (const float*)d_in[1];
    const float* ln1g = (const float*)d_in[2];
    const float* ln1b = (const float*)d_in[3];
    const float* Wq   = (const float*)d_in[4];
    const float* Wk   = (const float*)d_in[5];
    const float* Wv   = (const float*)d_in[6];
    const float* Wrel = (const float*)d_in[7];
    const float* rcb  = (const float*)d_in[8];
    const float* rpb  = (const float*)d_in[9];
    const float* Wo   = (const float*)d_in[10];
    const float* bo   = (const float*)d_in[11];
    const float* ln2g = (const float*)d_in[12];
    const float* ln2b = (const float*)d_in[13];
    const float* W1   = (const float*)d_in[14];
    const float* b1   = (const float*)d_in[15];
    const float* W2   = (const float*)d_in[16];
    const float* b2   = (const float*)d_in[17];
    float* out = (float*)d_out;

    const int ATT_SMEM   = 32768 + 32768 + 2048;  // 67584 B
    const int FUSED_SMEM = 14622 * 4;             // 58488 B
    const int PRO_SMEM   = 32768 + 22528 + 1024;  // 56320 B
    cudaFuncSetAttribute(attn_kernel,     cudaFuncAttributeMaxDynamicSharedMemorySize, ATT_SMEM);
    cudaFuncSetAttribute(fused_kernel,    cudaFuncAttributeMaxDynamicSharedMemorySize, FUSED_SMEM);
    cudaFuncSetAttribute(prologue_kernel, cudaFuncAttributeMaxDynamicSharedMemorySize, PRO_SMEM);

    cudaMemsetAsync(d_out, 0, (size_t)out_size * sizeof(float), 0);
    prologue_kernel<<<36, 1024, PRO_SMEM>>>(attention);
    sortgather_kernel<<<2, 256>>>(x_skip);
    posqkv_kernel<<<2176, 256>>>(ln1g, ln1b, Wq, Wk, Wv, Wrel, rcb, rpb);
    rel0_kernel<<<dim3(64, 2), 512>>>();

    for (int l = 0; l < 4; l++) {
        attn_kernel<<<dim3(32, 4, 2), 256, ATT_SMEM>>>();
        fused_kernel<<<dim3(64, 2), 512, FUSED_SMEM>>>(
            Wo, bo, ln2g, ln2b, W1, b1, W2, b2,
            ln1g, ln1b, Wq, Wk, Wv, Wrel, rcb, rpb, out,
            l, l + 1, /*do_qkv=*/(l < 3) ? 1 : 0);
    }
}

// round 16
// speedup vs baseline: 1.4103x; 1.0873x over previous
#include <cuda_runtime.h>
#include <cuda_fp16.h>
#include <math.h>

#define LSEQ 45000

// ---------------- device scratch (no allocs allowed) ----------------
__device__ uint4 d_posh4[1048576];          // [2][512][512] * 32B (16 halfs: 15 feats + sign)
__device__ int   d_topk[2][2][256];
__device__ int   d_idxg[2][512];
__device__ float d_emb[2*512*32];
__device__ __align__(16) __half d_kkh[2*4*32*512];   // [b*4+h][d][j] fp16
__device__ __align__(16) __half d_vvh[2*4*32*512];
__device__ float d_qcb[2*4*512*32];         // q*scale + rcb   [bh][i][d]
__device__ float d_qrl[2*512*4*32];         // layer-0 qrel only  [b][i][h][30 used]
__device__ __align__(16) __half d_relh[2*512*4*512]; // rel logits [b][i][h][j] fp16 (4MB)
__device__ float d_att[2*512*128];          // attention output pre-Wo
__device__ float d_cc[24];                  // 0..4 c1, 5..9 lz, 10..14 rate, 15..19 conc-1
__device__ int   d_pmaxbits;                // global gamma max (positive-float bits)

__device__ __forceinline__ __half2 u2h(unsigned u) { return *reinterpret_cast<__half2*>(&u); }
__device__ __forceinline__ unsigned h2u(__half2 h) { return *reinterpret_cast<unsigned*>(&h); }

// rel compute: warp = (row = w&7, jhalf = w>>3); qAh/qBh packed [ (r*4+h)*8 + p8 ]
__device__ __forceinline__ void compute_rel(const unsigned* qAh, const unsigned* qBh,
                                            int b, int i0, int t) {
    int lane = t & 31, w = t >> 5;
    int r = w & 7, jh = w >> 3;
    const uint4* prow = d_posh4 + 2 * (size_t)((b * 512 + i0 + r) * 512);
    unsigned* relbase = (unsigned*)d_relh;
    #pragma unroll
    for (int u2 = 0; u2 < 4; u2++) {
        int p = jh * 128 + u2 * 32 + lane;          // pair index, j = 2p, 2p+1
        uint4 A0 = prow[4 * p], B0 = prow[4 * p + 1];
        uint4 A1 = prow[4 * p + 2], B1 = prow[4 * p + 3];
        float sg0 = __high2float(u2h(B0.w));
        float sg1 = __high2float(u2h(B1.w));
        #pragma unroll
        for (int h = 0; h < 4; h++) {
            const unsigned* qa = qAh + (r * 4 + h) * 8;
            const unsigned* qb = qBh + (r * 4 + h) * 8;
            float v0, v1;
            {
                __half2 sA = __hmul2(u2h(A0.x), u2h(qa[0]));
                sA = __hfma2(u2h(A0.y), u2h(qa[1]), sA); sA = __hfma2(u2h(A0.z), u2h(qa[2]), sA);
                sA = __hfma2(u2h(A0.w), u2h(qa[3]), sA); sA = __hfma2(u2h(B0.x), u2h(qa[4]), sA);
                sA = __hfma2(u2h(B0.y), u2h(qa[5]), sA); sA = __hfma2(u2h(B0.z), u2h(qa[6]), sA);
                sA = __hfma2(u2h(B0.w), u2h(qa[7]), sA);
                __half2 sB = __hmul2(u2h(A0.x), u2h(qb[0]));
                sB = __hfma2(u2h(A0.y), u2h(qb[1]), sB); sB = __hfma2(u2h(A0.z), u2h(qb[2]), sB);
                sB = __hfma2(u2h(A0.w), u2h(qb[3]), sB); sB = __hfma2(u2h(B0.x), u2h(qb[4]), sB);
                sB = __hfma2(u2h(B0.y), u2h(qb[5]), sB); sB = __hfma2(u2h(B0.z), u2h(qb[6]), sB);
                sB = __hfma2(u2h(B0.w), u2h(qb[7]), sB);
                float2 fA = __half22float2(sA), fB = __half22float2(sB);
                v0 = (fA.x + fA.y) + sg0 * (fB.x + fB.y);
            }
            {
                __half2 sA = __hmul2(u2h(A1.x), u2h(qa[0]));
                sA = __hfma2(u2h(A1.y), u2h(qa[1]), sA); sA = __hfma2(u2h(A1.z), u2h(qa[2]), sA);
                sA = __hfma2(u2h(A1.w), u2h(qa[3]), sA); sA = __hfma2(u2h(B1.x), u2h(qa[4]), sA);
                sA = __hfma2(u2h(B1.y), u2h(qa[5]), sA); sA = __hfma2(u2h(B1.z), u2h(qa[6]), sA);
                sA = __hfma2(u2h(B1.w), u2h(qa[7]), sA);
                __half2 sB = __hmul2(u2h(A1.x), u2h(qb[0]));
                sB = __hfma2(u2h(A1.y), u2h(qb[1]), sB); sB = __hfma2(u2h(A1.z), u2h(qb[2]), sB);
                sB = __hfma2(u2h(A1.w), u2h(qb[3]), sB); sB = __hfma2(u2h(B1.x), u2h(qb[4]), sB);
                sB = __hfma2(u2h(B1.y), u2h(qb[5]), sB); sB = __hfma2(u2h(B1.z), u2h(qb[6]), sB);
                sB = __hfma2(u2h(B1.w), u2h(qb[7]), sB);
                float2 fA = __half22float2(sA), fB = __half22float2(sB);
                v1 = (fA.x + fA.y) + sg1 * (fB.x + fB.y);
            }
            relbase[((size_t)((b * 512 + i0 + r) * 4 + h)) * 256 + p] = h2u(__floats2half2_rn(v0, v1));
        }
    }
}

// ---------------- prologue: blocks 0-3 top-256 select, blocks 4-35 basis setup ----------------
#define TK_CAP 2816
__global__ void __launch_bounds__(1024) prologue_kernel(const float* __restrict__ att) {
    extern __shared__ unsigned char tks[];
    int t = threadIdx.x, lane = t & 31;

    if (blockIdx.x >= 4) {
        float* red = (float*)tks;
        int bid = blockIdx.x - 4;
        double L2S = log(45000.0) / log(2.0);
        float c1[5], lz[5], rate[5], cm1[5];
        for (int k = 0; k < 5; k++) {
            double lin = 3.0 + (L2S - 3.0) * ((double)k / 4.0);
            float hl = (float)exp2(lin);
            c1[k] = -0.69314718055994531f / hl;
            double mean = 9000.0 * (k + 1);
            double sd = 4500.0;
            float conc = (float)((mean / sd) * (mean / sd));
            float rt = (float)(mean / (sd * sd));
            rate[k] = rt; cm1[k] = conc - 1.0f;
            lz[k] = lgammaf(conc) - conc * logf(rt);
        }
        float m = 1e-8f;
        for (int a_ = bid * 1024 + t; a_ < LSEQ; a_ += 32768) {
            if (a_ == 0) continue;
            float a = (float)a_;
            float la = logf(a);
            for (int k = 0; k < 5; k++) {
                float p = expf(cm1[k] * la - rate[k] * a - lz[k]) + 1e-8f;
                m = fmaxf(m, p);
            }
        }
        red[t] = m; __syncthreads();
        for (int s = 512; s > 0; s >>= 1) {
            if (t < s) red[t] = fmaxf(red[t], red[t + s]);
            __syncthreads();
        }
        if (t == 0) atomicMax(&d_pmaxbits, __float_as_int(red[0]));
        if (bid == 0 && t == 0) {
            for (int k = 0; k < 5; k++) { d_cc[k] = c1[k]; d_cc[5+k] = lz[k]; d_cc[10+k] = rate[k]; d_cc[15+k] = cm1[k]; }
        }
        return;
    }

    unsigned* hist = (unsigned*)tks;
    unsigned long long* cand = (unsigned long long*)(tks + 32768);
    unsigned* ps = (unsigned*)(tks + 32768 + 22528);
    __shared__ unsigned thrT;
    __shared__ int cnt, ocnt, rem_s;
    __shared__ unsigned long long pref_s;
    int b = blockIdx.x >> 1, ch = (blockIdx.x & 1) + 1;
    const float* vals = att + (size_t)(b * 3 + ch) * LSEQ;
    for (int i = t; i < 8192; i += 1024) hist[i] = 0;
    if (t == 0) { cnt = 0; ocnt = 0; pref_s = 0ull; rem_s = 256; }
    __syncthreads();
    for (int j = t; j < LSEQ; j += 1024) {
        unsigned u = __float_as_uint(vals[j]);
        u = (u & 0x80000000u) ? ~u : (u | 0x80000000u);
        atomicAdd(&hist[u >> 19], 1u);
    }
    __syncthreads();
    if (t < 256) {
        unsigned sum = 0;
        int base = 8191 - t * 32;
        for (int k = 0; k < 32; k++) sum += hist[base - k];
        ps[t] = sum;
    }
    __syncthreads();
    if (t < 32) {
        unsigned s = 0;
        #pragma unroll
        for (int k = 0; k < 8; k++) s += ps[lane * 8 + k];
        unsigned pre = s;
        #pragma unroll
        for (int o = 1; o < 32; o <<= 1) { unsigned v = __shfl_up_sync(0xffffffffu, pre, o); if (lane >= o) pre += v; }
        bool hit = (pre >= 256u) && (pre - s) < 256u;
        unsigned mk = __ballot_sync(0xffffffffu, hit);
        if (lane == (__ffs(mk) - 1)) {
            unsigned cum = pre - s;
            int T = 0;
            for (int k = 0; k < 8; k++) {
                int ci = lane * 8 + k;
                if (cum + ps[ci] >= 256u) {
                    int base = 8191 - ci * 32;
                    for (int kk = 0; kk < 32; kk++) { cum += hist[base - kk]; if (cum >= 256u) { T = base - kk; break; } }
                    break;
                }
                cum += ps[ci];
            }
            thrT = (unsigned)T;
        }
    }
    __syncthreads();
    unsigned T = thrT;
    for (int j = t; j < LSEQ; j += 1024) {
        unsigned u = __float_as_uint(vals[j]);
        u = (u & 0x80000000u) ? ~u : (u | 0x80000000u);
        if ((u >> 19) >= T) {
            int pi = atomicAdd(&cnt, 1);
            if (pi < TK_CAP) cand[pi] = (((unsigned long long)u) << 32) | (unsigned)(0xFFFFFFFFu - (unsigned)j);
        }
    }
    __syncthreads();
    int n = cnt < TK_CAP ? cnt : TK_CAP;
    for (int shift = 56; shift >= 0; shift -= 8) {
        if (t < 256) hist[t] = 0;
        __syncthreads();
        unsigned long long p = pref_s;
        unsigned long long mh = (shift == 56) ? 0ull : ~((1ull << (shift + 8)) - 1ull);
        for (int i = t; i < n; i += 1024) {
            unsigned long long k = cand[i];
            if ((k & mh) == p) atomicAdd(&hist[(unsigned)(k >> shift) & 255u], 1u);
        }
        __syncthreads();
        if (t < 32) {
            int r = rem_s;
            unsigned s = 0;
            #pragma unroll
            for (int k = 0; k < 8; k++) s += hist[255 - (lane * 8 + k)];
            unsigned pre = s;
            #pragma unroll
            for (int o = 1; o < 32; o <<= 1) { unsigned v = __shfl_up_sync(0xffffffffu, pre, o); if (lane >= o) pre += v; }
            bool hit = ((int)pre >= r) && (int)(pre - s) < r;
            unsigned mk = __ballot_sync(0xffffffffu, hit);
            if (lane == (__ffs(mk) - 1)) {
                unsigned cum = pre - s;
                for (int k = 0; k < 8; k++) {
                    int bin = 255 - (lane * 8 + k);
                    cum += hist[bin];
                    if ((int)cum >= r) { rem_s = r - (int)(cum - hist[bin]); pref_s = p | ((unsigned long long)bin << shift); break; }
                }
            }
        }
        __syncthreads();
    }
    unsigned long long kth = pref_s;
    for (int i = t; i < n; i += 1024) {
        if (cand[i] >= kth) {
            int pi = atomicAdd(&ocnt, 1);
            if (pi < 256) d_topk[b][ch - 1][pi] = (int)(0xFFFFFFFFu - (unsigned)(cand[i] & 0xFFFFFFFFull));
        }
    }
}

// ---------------- merge+sort 512 indices, gather embeddings ----------------
__global__ void __launch_bounds__(256) sortgather_kernel(const float* __restrict__ x_skip) {
    int b = blockIdx.x, t = threadIdx.x;
    __shared__ int s[512];
    s[t] = d_topk[b][0][t];
    s[256 + t] = d_topk[b][1][t];
    __syncthreads();
    for (int k = 2; k <= 512; k <<= 1) {
        for (int j = k >> 1; j > 0; j >>= 1) {
            #pragma unroll
            for (int half = 0; half < 2; half++) {
                int idx = half * 256 + t;
                int ixj = idx ^ j;
                if (ixj > idx) {
                    int a = s[idx], c = s[ixj];
                    bool up = ((idx & k) == 0);
                    if ((a > c) == up) { s[idx] = c; s[ixj] = a; }
                }
            }
            __syncthreads();
        }
    }
    d_idxg[b][t] = s[t];
    d_idxg[b][256 + t] = s[256 + t];
    __syncthreads();
    for (int q = t; q < 512 * 32; q += 256) {
        int i = q >> 5, c = q & 31;
        d_emb[(b * 512 + i) * 32 + c] = x_skip[((size_t)b * 32 + c) * LSEQ + s[i]];
    }
}

// ---------------- hybrid: blocks 0-2047 pos features; blocks 2048-2175 qkv layer 0 ----------------
__global__ void __launch_bounds__(256) posqkv_kernel(
    const float* __restrict__ ln1g, const float* __restrict__ ln1b,
    const float* __restrict__ Wq, const float* __restrict__ Wk, const float* __restrict__ Wv,
    const float* __restrict__ Wrel, const float* __restrict__ rcb, const float* __restrict__ rpb)
{
    __shared__ float h2s[256];
    __shared__ float qp[1024];
    __shared__ float Wrs[3870];
    int t = threadIdx.x, lane = t & 31, w = t >> 5;

    if (blockIdx.x < 2048) {
        unsigned int id = blockIdx.x * 256u + t;
        int b = id >> 18;
        unsigned int r = id & 262143u;
        int i = r >> 9, j = r & 511;
        int d = d_idxg[b][i] - d_idxg[b][j];
        float a = fabsf((float)d);
        float sg = (d > 0) ? 1.f : ((d < 0) ? -1.f : 0.f);
        float f[16];
        #pragma unroll
        for (int k = 0; k < 5; k++) f[k] = expf(d_cc[k] * a);
        f[5] = (1.f  > a) ? 1.f : 0.f;
        f[6] = (3.f  > a) ? 1.f : 0.f;
        f[7] = (7.f  > a) ? 1.f : 0.f;
        f[8] = (15.f > a) ? 1.f : 0.f;
        f[9] = (31.f > a) ? 1.f : 0.f;
        float la = logf(a);
        float invp = 1.0f / __int_as_float(d_pmaxbits);
        #pragma unroll
        for (int k = 0; k < 5; k++) {
            float lp = d_cc[15 + k] * la - d_cc[10 + k] * a;
            f[10 + k] = (expf(lp - d_cc[5 + k]) + 1e-8f) * invp;
        }
        f[15] = sg;
        unsigned u[8];
        #pragma unroll
        for (int k = 0; k < 8; k++) u[k] = h2u(__floats2half2_rn(f[2 * k], f[2 * k + 1]));
        uint4* o = d_posh4 + (size_t)id * 2u;
        o[0] = make_uint4(u[0], u[1], u[2], u[3]);
        o[1] = make_uint4(u[4], u[5], u[6], u[7]);
        return;
    }

    int q = blockIdx.x - 2048;            // 0..127
    int b = q >> 6, i0 = (q & 63) * 8;

    for (int qq = t; qq < 3840; qq += 256) {
        int f = qq >> 7, c = qq & 127;
        Wrs[f * 129 + c] = Wrel[qq];      // lq = 0
    }
    {
        float x = d_emb[(b * 512 + i0 + w) * 32 + lane];
        float s1 = x;
        #pragma unroll
        for (int o = 16; o > 0; o >>= 1) s1 += __shfl_xor_sync(0xffffffffu, s1, o);
        float mu = s1 * (1.f / 32.f);
        float dd = x - mu;
        float s2 = dd * dd;
        #pragma unroll
        for (int o = 16; o > 0; o >>= 1) s2 += __shfl_xor_sync(0xffffffffu, s2, o);
        float rs = rsqrtf(s2 * (1.f / 32.f) + 1e-5f);
        h2s[w * 32 + lane] = dd * rs * ln1g[lane] + ln1b[lane];
    }
    __syncthreads();
    {
        int c = t & 127, tg = t >> 7;
        int hh = c >> 5, dd = c & 31;
        int bh = b * 4 + hh;
        float rc = rcb[hh * 32 + dd];
        float rp = rpb[hh * 32 + dd];
        float accq[4], acck[4], accv[4];
        #pragma unroll
        for (int tk = 0; tk < 4; tk++) { accq[tk] = 0.f; acck[tk] = 0.f; accv[tk] = 0.f; }
        #pragma unroll 8
        for (int cc = 0; cc < 32; cc++) {
            float a = Wq[cc * 128 + c], kwe = Wk[cc * 128 + c], vwe = Wv[cc * 128 + c];
            #pragma unroll
            for (int tk = 0; tk < 4; tk++) {
                float hc = h2s[(tg * 4 + tk) * 32 + cc];
                accq[tk] += hc * a; acck[tk] += hc * kwe; accv[tk] += hc * vwe;
            }
        }
        #pragma unroll
        for (int tk = 0; tk < 4; tk++) {
            int tok = tg * 4 + tk;
            float qv = accq[tk] * 0.17677669529663687f;
            d_qcb[(bh * 512 + i0 + tok) * 32 + dd] = qv + rc;
            qp[tok * 128 + c] = qv + rp;
        }
        uint2 kp, vp;
        kp.x = h2u(__floats2half2_rn(acck[0], acck[1]));
        kp.y = h2u(__floats2half2_rn(acck[2], acck[3]));
        vp.x = h2u(__floats2half2_rn(accv[0], accv[1]));
        vp.y = h2u(__floats2half2_rn(accv[2], accv[3]));
        *(uint2*)&d_kkh[(bh * 32 + dd) * 512 + i0 + tg * 4] = kp;
        *(uint2*)&d_vvh[(bh * 32 + dd) * 512 + i0 + tg * 4] = vp;
    }
    __syncthreads();
    if (lane < 30) {
        int f = lane, tok = w;
        #pragma unroll
        for (int h2 = 0; h2 < 4; h2++) {
            float s = 0.f;
            #pragma unroll
            for (int d2 = 0; d2 < 32; d2++)
                s += Wrs[f * 129 + h2 * 32 + d2] * qp[tok * 128 + h2 * 32 + d2];
            d_qrl[((b * 512 + i0 + tok) * 4 + h2) * 32 + f] = s;
        }
    }
}

// ---------------- rel for layer 0 (reads d_qrl written by posqkv) ----------------
__global__ void __launch_bounds__(512) rel0_kernel() {
    __shared__ unsigned qAh[256], qBh[256];
    int t = threadIdx.x;
    int i0 = blockIdx.x * 8, b = blockIdx.y;
    if (t < 256) {
        int unit = t >> 3, p8 = t & 7;
        int r = unit >> 2, h = unit & 3;
        const float* qr = d_qrl + ((b * 512 + i0 + r) * 4 + h) * 32;
        int f0 = 2 * p8, f1 = f0 + 1;
        float a0 = qr[f0],      a1 = (f1 < 15) ? qr[f1] : 0.f;
        float b0 = qr[15 + f0], b1 = (f1 < 15) ? qr[15 + f1] : 0.f;
        qAh[unit * 8 + p8] = h2u(__floats2half2_rn(a0, a1));
        qBh[unit * 8 + p8] = h2u(__floats2half2_rn(b0, b1));
    }
    __syncthreads();
    compute_rel(qAh, qBh, b, i0, t);
}

// ---------------- attention: 16 rows/block, 2 rows/warp, HFMA2 pair-packed QK/PV ----------------
__global__ void __launch_bounds__(256, 2) attn_kernel() {
    extern __shared__ __align__(16) unsigned char smraw[];
    __half* Kh = (__half*)smraw;                       // 32KB [d][j]
    __half* Vh = (__half*)(smraw + 32768);             // 32KB
    unsigned* qch = (unsigned*)(smraw + 65536);        // 512 u (splatted half2 q)
    int t = threadIdx.x, lane = t & 31, w = t >> 5;
    int i0 = blockIdx.x * 16;
    int hd = blockIdx.y;
    int b = blockIdx.z;
    int bh = b * 4 + hd;

    {
        const uint4* kg = (const uint4*)(d_kkh + bh * 16384);
        const uint4* vg = (const uint4*)(d_vvh + bh * 16384);
        uint4* ks4 = (uint4*)Kh; uint4* vs4 = (uint4*)Vh;
        for (int q = t; q < 2048; q += 256) { ks4[q] = kg[q]; vs4[q] = vg[q]; }
    }
    for (int q = t; q < 512; q += 256) {
        float v = d_qcb[(bh * 512 + i0 + (q >> 5)) * 32 + (q & 31)];
        qch[q] = h2u(__floats2half2_rn(v, v));
    }
    __syncthreads();

    int r0 = 2 * w, r1 = r0 + 1;
    // pair mapping: pr = ch*2+u2; p_global = ch*64 + u2*32 + lane; j = 2p (low), 2p+1 (high)
    float s0[16], s1[16];
    #pragma unroll
    for (int q = 0; q < 16; q++) { s0[q] = 0.f; s1[q] = 0.f; }

    // QK: HFMA2 per pair, fp16 partials promoted every 8-d chunk
    #pragma unroll
    for (int c8 = 0; c8 < 4; c8++) {
        __half2 a0[8], a1[8];
        #pragma unroll
        for (int pr = 0; pr < 8; pr++) { a0[pr] = __floats2half2_rn(0.f, 0.f); a1[pr] = a0[pr]; }
        #pragma unroll
        for (int dd = 0; dd < 8; dd++) {
            int d = c8 * 8 + dd;
            __half2 qv0 = u2h(qch[r0 * 32 + d]);
            __half2 qv1 = u2h(qch[r1 * 32 + d]);
            const unsigned* kr = (const unsigned*)(Kh + d * 512);
            #pragma unroll
            for (int pr = 0; pr < 8; pr++) {
                __half2 kk = u2h(kr[(pr >> 1) * 64 + (pr & 1) * 32 + lane]);
                a0[pr] = __hfma2(kk, qv0, a0[pr]);
                a1[pr] = __hfma2(kk, qv1, a1[pr]);
            }
        }
        #pragma unroll
        for (int pr = 0; pr < 8; pr++) {
            float2 f0 = __half22float2(a0[pr]);
            float2 f1 = __half22float2(a1[pr]);
            s0[2 * pr] += f0.x; s0[2 * pr + 1] += f0.y;
            s1[2 * pr] += f1.x; s1[2 * pr + 1] += f1.y;
        }
    }
    // rel add (coalesced fp16 rows)
    {
        const unsigned* rr0 = (const unsigned*)d_relh + ((size_t)((b * 512 + i0 + r0) * 4 + hd)) * 256;
        const unsigned* rr1 = (const unsigned*)d_relh + ((size_t)((b * 512 + i0 + r1) * 4 + hd)) * 256;
        #pragma unroll
        for (int pr = 0; pr < 8; pr++) {
            int p = (pr >> 1) * 64 + (pr & 1) * 32 + lane;
            float2 f0 = __half22float2(u2h(rr0[p]));
            float2 f1 = __half22float2(u2h(rr1[p]));
            s0[2 * pr] += f0.x; s0[2 * pr + 1] += f0.y;
            s1[2 * pr] += f1.x; s1[2 * pr + 1] += f1.y;
        }
    }

    float m0 = -3.0e38f, m1 = -3.0e38f;
    #pragma unroll
    for (int q = 0; q < 16; q++) { m0 = fmaxf(m0, s0[q]); m1 = fmaxf(m1, s1[q]); }
    #pragma unroll
    for (int o = 16; o > 0; o >>= 1) {
        m0 = fmaxf(m0, __shfl_xor_sync(0xffffffffu, m0, o));
        m1 = fmaxf(m1, __shfl_xor_sync(0xffffffffu, m1, o));
    }
    float su0 = 0.f, su1 = 0.f;
    #pragma unroll
    for (int q = 0; q < 16; q++) {
        s0[q] = expf(s0[q] - m0); su0 += s0[q];
        s1[q] = expf(s1[q] - m1); su1 += s1[q];
    }
    #pragma unroll
    for (int o = 16; o > 0; o >>= 1) {
        su0 += __shfl_xor_sync(0xffffffffu, su0, o);
        su1 += __shfl_xor_sync(0xffffffffu, su1, o);
    }
    float inv0 = 1.f / su0, inv1 = 1.f / su1;

    // pack softmax weights per pair (unnormalized; inv applied at end)
    __half2 ph0[8], ph1[8];
    #pragma unroll
    for (int pr = 0; pr < 8; pr++) {
        ph0[pr] = __floats2half2_rn(s0[2 * pr], s0[2 * pr + 1]);
        ph1[pr] = __floats2half2_rn(s1[2 * pr], s1[2 * pr + 1]);
    }

    // PV: HFMA2 per pair, single promote per d
    #pragma unroll
    for (int pass = 0; pass < 2; pass++) {
        float v[32];
        #pragma unroll
        for (int k = 0; k < 16; k++) {
            int d = pass * 16 + k;
            const unsigned* vr = (const unsigned*)(Vh + d * 512);
            __half2 acc0 = __floats2half2_rn(0.f, 0.f);
            __half2 acc1 = acc0;
            #pragma unroll
            for (int pr = 0; pr < 8; pr++) {
                __half2 vv = u2h(vr[(pr >> 1) * 64 + (pr & 1) * 32 + lane]);
                acc0 = __hfma2(vv, ph0[pr], acc0);
                acc1 = __hfma2(vv, ph1[pr], acc1);
            }
            float2 f0 = __half22float2(acc0);
            float2 f1 = __half22float2(acc1);
            v[k] = f0.x + f0.y;
            v[16 + k] = f1.x + f1.y;
        }
        #pragma unroll
        for (int m = 16; m >= 1; m >>= 1) {
            #pragma unroll
            for (int k = 0; k < m; k++) {
                float give = (lane & m) ? v[k] : v[k + m];
                float got = __shfl_xor_sync(0xffffffffu, give, m);
                v[k] = (lane & m) ? (v[k + m] + got) : (v[k] + got);
            }
        }
        float outv = v[0] * ((lane < 16) ? inv0 : inv1);
        int row = (lane < 16) ? r0 : r1;
        int dd = (lane & 15) + pass * 16;
        d_att[(b * 512 + i0 + row) * 128 + hd * 32 + dd] = outv;
    }
}

// ---------------- fused: mlp(lm) + qkv(lq) + rel(lq), 8 tokens/block, 512 threads ----------------
__global__ void __launch_bounds__(512, 1) fused_kernel(
    const float* __restrict__ Wo, const float* __restrict__ bo,
    const float* __restrict__ ln2g, const float* __restrict__ ln2b,
    const float* __restrict__ W1, const float* __restrict__ b1,
    const float* __restrict__ W2, const float* __restrict__ b2,
    const float* __restrict__ ln1g, const float* __restrict__ ln1b,
    const float* __restrict__ Wq, const float* __restrict__ Wk, const float* __restrict__ Wv,
    const float* __restrict__ Wrel, const float* __restrict__ rcb, const float* __restrict__ rpb,
    float* __restrict__ out,
    int lm, int lq, int do_qkv)
{
    extern __shared__ float sm[];
    float* ats = sm;                  // 1024
    float* es  = sm + 1024;           // 256
    float* h2s = sm + 1280;           // 256
    float* tbs = sm + 1536;           // 4096 (reused: qrs floats)
    float* red = sm + 5632;           // 4096 (reused: qAh/qBh)
    float* qp  = sm + 9728;           // 1024
    float* Wrs = sm + 10752;          // 3870 -> 14622 floats total
    int t = threadIdx.x, lane = t & 31, w = t >> 5;
    int i0 = blockIdx.x * 8, b = blockIdx.y;

    if (do_qkv) {
        for (int q = t; q < 3840; q += 512) {
            int f = q >> 7, c = q & 127;
            Wrs[f * 129 + c] = Wrel[lq * 3840 + q];
        }
    }

    {
        for (int q = t; q < 1024; q += 512) ats[q] = d_att[(b * 512 + i0) * 128 + q];
        __syncthreads();
        {
            int oi = t >> 1, hf = t & 1;
            int tok = oi >> 5, c = oi & 31;
            const float* wo = Wo + lm * 4096;
            int mb = hf * 64;
            float acc = 0.f;
            #pragma unroll 16
            for (int m = 0; m < 64; m++) acc += ats[tok * 128 + mb + m] * wo[(mb + m) * 32 + c];
            acc += __shfl_xor_sync(0xffffffffu, acc, 1);
            if (hf == 0) es[oi] = d_emb[(b * 512 + i0 + tok) * 32 + c] + acc + bo[lm * 32 + c];
        }
        __syncthreads();
        if (w < 8) {
            float x = es[w * 32 + lane];
            float s1 = x;
            #pragma unroll
            for (int o = 16; o > 0; o >>= 1) s1 += __shfl_xor_sync(0xffffffffu, s1, o);
            float mu = s1 * (1.f / 32.f);
            float dd = x - mu;
            float s2 = dd * dd;
            #pragma unroll
            for (int o = 16; o > 0; o >>= 1) s2 += __shfl_xor_sync(0xffffffffu, s2, o);
            float rs = rsqrtf(s2 * (1.f / 32.f) + 1e-5f);
            h2s[w * 32 + lane] = dd * rs * ln2g[lm * 32 + lane] + ln2b[lm * 32 + lane];
        }
        __syncthreads();
        {
            int m = t;
            const float* w1 = W1 + lm * 16384;
            float wcol[32];
            #pragma unroll
            for (int cc = 0; cc < 32; cc++) wcol[cc] = w1[cc * 512 + m];
            float bb = b1[lm * 512 + m];
            #pragma unroll
            for (int tok = 0; tok < 8; tok++) {
                float s = bb;
                #pragma unroll
                for (int cc = 0; cc < 32; cc++) s += h2s[tok * 32 + cc] * wcol[cc];
                tbs[tok * 512 + m] = 0.5f * s * (1.f + erff(s * 0.70710678118654752f));
            }
        }
        __syncthreads();
        {
            const float* w2 = W2 + lm * 16384;
            int m0 = w * 32;
            float accw[8];
            #pragma unroll
            for (int tok = 0; tok < 8; tok++) accw[tok] = 0.f;
            #pragma unroll 4
            for (int mm = 0; mm < 32; mm++) {
                float w2v = w2[(m0 + mm) * 32 + lane];
                #pragma unroll
                for (int tok = 0; tok < 8; tok++) accw[tok] += tbs[tok * 512 + m0 + mm] * w2v;
            }
            #pragma unroll
            for (int tok = 0; tok < 8; tok++) red[(w * 8 + tok) * 32 + lane] = accw[tok];
        }
        __syncthreads();
        if (t < 256) {
            int tok = t >> 5, c = t & 31;
            float s = 0.f;
            #pragma unroll
            for (int ww = 0; ww < 16; ww++) s += red[(ww * 8 + tok) * 32 + c];
            float ne = es[t] + s + b2[lm * 32 + c];
            if (do_qkv) {
                d_emb[(b * 512 + i0 + tok) * 32 + c] = ne;
                es[t] = ne;
            } else {
                out[((size_t)b * 32 + c) * LSEQ + d_idxg[b][i0 + tok]] = ne;
            }
        }
    }
    __syncthreads();

    if (!do_qkv) return;

    if (w < 8) {
        float x = es[w * 32 + lane];
        float s1 = x;
        #pragma unroll
        for (int o = 16; o > 0; o >>= 1) s1 += __shfl_xor_sync(0xffffffffu, s1, o);
        float mu = s1 * (1.f / 32.f);
        float dd = x - mu;
        float s2 = dd * dd;
        #pragma unroll
        for (int o = 16; o > 0; o >>= 1) s2 += __shfl_xor_sync(0xffffffffu, s2, o);
        float rs = rsqrtf(s2 * (1.f / 32.f) + 1e-5f);
        h2s[w * 32 + lane] = dd * rs * ln1g[lq * 32 + lane] + ln1b[lq * 32 + lane];
    }
    __syncthreads();
    {
        int c = t & 127, tg = t >> 7;
        int hh = c >> 5, dd = c & 31;
        int bh = b * 4 + hh;
        float rc = rcb[(lq * 4 + hh) * 32 + dd];
        float rp = rpb[(lq * 4 + hh) * 32 + dd];
        const float* wq = Wq + lq * 4096;
        const float* wk = Wk + lq * 4096;
        const float* wv = Wv + lq * 4096;
        float accq[2] = {0.f, 0.f}, acck[2] = {0.f, 0.f}, accv[2] = {0.f, 0.f};
        #pragma unroll 8
        for (int cc = 0; cc < 32; cc++) {
            float a = wq[cc * 128 + c], kwe = wk[cc * 128 + c], vwe = wv[cc * 128 + c];
            #pragma unroll
            for (int tk = 0; tk < 2; tk++) {
                float hc = h2s[(tg * 2 + tk) * 32 + cc];
                accq[tk] += hc * a; acck[tk] += hc * kwe; accv[tk] += hc * vwe;
            }
        }
        #pragma unroll
        for (int tk = 0; tk < 2; tk++) {
            int tok = tg * 2 + tk;
            float q = accq[tk] * 0.17677669529663687f;
            d_qcb[(bh * 512 + i0 + tok) * 32 + dd] = q + rc;
            qp[tok * 128 + c] = q + rp;
        }
        *(unsigned*)&d_kkh[(bh * 32 + dd) * 512 + i0 + tg * 2] = h2u(__floats2half2_rn(acck[0], acck[1]));
        *(unsigned*)&d_vvh[(bh * 32 + dd) * 512 + i0 + tg * 2] = h2u(__floats2half2_rn(accv[0], accv[1]));
    }
    __syncthreads();
    // qrel into smem qrs (tbs reuse)
    float* qrs = tbs;     // [ (tok*4+h)*32 + f ]
    if (lane < 30) {
        int f = lane, tok = w >> 1, h2b = (w & 1) * 2;
        #pragma unroll
        for (int k = 0; k < 2; k++) {
            int hh2 = h2b + k;
            float s = 0.f;
            #pragma unroll
            for (int d2 = 0; d2 < 32; d2++)
                s += Wrs[f * 129 + hh2 * 32 + d2] * qp[tok * 128 + hh2 * 32 + d2];
            qrs[(tok * 4 + hh2) * 32 + f] = s;
        }
    }
    __syncthreads();
    // pack half2 q-vectors
    unsigned* qAh = (unsigned*)red;
    unsigned* qBh = qAh + 256;
    if (t < 256) {
        int unit = t >> 3, p8 = t & 7;
        int f0 = 2 * p8, f1 = f0 + 1;
        float a0 = qrs[unit * 32 + f0],      a1 = (f1 < 15) ? qrs[unit * 32 + f1] : 0.f;
        float b0 = qrs[unit * 32 + 15 + f0], b1 = (f1 < 15) ? qrs[unit * 32 + 15 + f1] : 0.f;
        qAh[unit * 8 + p8] = h2u(__floats2half2_rn(a0, a1));
        qBh[unit * 8 + p8] = h2u(__floats2half2_rn(b0, b1));
    }
    __syncthreads();
    compute_rel(qAh, qBh, b, i0, t);
}

// ---------------- launch ----------------
extern "C" void kernel_launch(void* const* d_in, const int* in_sizes, int n_in,
                              void* d_out, int out_size) {
    (void)in_sizes; (void)n_in;
    const float* x_skip    = (const float*)d_in[0];
    const float* attention = (const float*)d_in[1];
    const float* ln1g = (const float*)d_in[2];
    const float* ln1b = (const float*)d_in[3];
    const float* Wq   = (const float*)d_in[4];
    const float* Wk   = (const float*)d_in[5];
    const float* Wv   = (const float*)d_in[6];
    const float* Wrel = (const float*)d_in[7];
    const float* rcb  = (const float*)d_in[8];
    const float* rpb  = (const float*)d_in[9];
    const float* Wo   = (const float*)d_in[10];
    const float* bo   = (const float*)d_in[11];
    const float* ln2g = (const float*)d_in[12];
    const float* ln2b = (const float*)d_in[13];
    const float* W1   = (const float*)d_in[14];
    const float* b1   = (const float*)d_in[15];
    const float* W2   = (const float*)d_in[16];
    const float* b2   = (const float*)d_in[17];
    float* out = (float*)d_out;

    const int ATT_SMEM   = 32768 + 32768 + 2048;  // 67584 B
    const int FUSED_SMEM = 14622 * 4;             // 58488 B
    const int PRO_SMEM   = 32768 + 22528 + 1024;  // 56320 B
    cudaFuncSetAttribute(attn_kernel,     cudaFuncAttributeMaxDynamicSharedMemorySize, ATT_SMEM);
    cudaFuncSetAttribute(fused_kernel,    cudaFuncAttributeMaxDynamicSharedMemorySize, FUSED_SMEM);
    cudaFuncSetAttribute(prologue_kernel, cudaFuncAttributeMaxDynamicSharedMemorySize, PRO_SMEM);

    cudaMemsetAsync(d_out, 0, (size_t)out_size * sizeof(float), 0);
    prologue_kernel<<<36, 1024, PRO_SMEM>>>(attention);
    sortgather_kernel<<<2, 256>>>(x_skip);
    posqkv_kernel<<<2176, 256>>>(ln1g, ln1b, Wq, Wk, Wv, Wrel, rcb, rpb);
    rel0_kernel<<<dim3(64, 2), 512>>>();

    for (int l = 0; l < 4; l++) {
        attn_kernel<<<dim3(32, 4, 2), 256, ATT_SMEM>>>();
        fused_kernel<<<dim3(64, 2), 512, FUSED_SMEM>>>(
            Wo, bo, ln2g, ln2b, W1, b1, W2, b2,
            ln1g, ln1b, Wq, Wk, Wv, Wrel, rcb, rpb, out,
            l, l + 1, /*do_qkv=*/(l < 3) ? 1 : 0);
    }
}